// round 1
// baseline (speedup 1.0000x reference)
#include <cuda_runtime.h>
#include <mma.h>
#include <cstdint>
#include <cstdio>

using namespace nvcuda;

#define T_STEPS 256
#define BATCH   512
#define DIM     512
#define HID     512
#define NQV     8
#define NTOT    2048   // 4*HID
#define ALPHA_F 0.7f
#define ALPHB_F 0.3f

// ---------------- scratch (device globals; no allocations allowed) ----------
__device__ float g_XP[(size_t)T_STEPS * BATCH * NTOT];   // 1.07 GB: x-part preactivations + bias
__device__ float g_XQ[(size_t)T_STEPS * BATCH * NQV];    // 4 MB:  x-part of q_in + bias
__device__ float g_hx[BATCH * HID];
__device__ float g_cx[BATCH * HID];

__device__ __forceinline__ float to_tf32(float x) {
    float r; asm("cvt.rna.tf32.f32 %0, %1;" : "=f"(r) : "f"(x)); return r;
}
__device__ __forceinline__ float sigm(float x) { return 1.f / (1.f + expf(-x)); }

// ---------------- zero recurrent state (graph-replay determinism) -----------
__global__ void zero_state() {
    int i = blockIdx.x * blockDim.x + threadIdx.x;
    if (i < BATCH * HID) { g_hx[i] = 0.f; g_cx[i] = 0.f; }
}

// ---------------- 3xTF32 GEMM: C[M x 2048] (+)= A[M x 512] * W_gate + bias --
// A row-major, lda=512. W per gate: (1024 x 512) row-major; rows [krow_off, krow_off+512).
// accumulate=0: C = A*W + bias ; accumulate=1: C += A*W
__global__ void __launch_bounds__(256) gemm3tf32(
    const float* __restrict__ A, int krow_off,
    const float* __restrict__ W0, const float* __restrict__ W1,
    const float* __restrict__ W2, const float* __restrict__ W3,
    const float* __restrict__ b0, const float* __restrict__ b1,
    const float* __restrict__ b2, const float* __restrict__ b3,
    float* __restrict__ C, int accumulate)
{
    __shared__ float pool[8192];           // 32 KB, aliased: tiles then C-tile
    float* sAhi = pool;                    // 128 x 16
    float* sAlo = pool + 2048;
    float* sBhi = pool + 4096;             // 16 x 64
    float* sBlo = pool + 5120;

    const int tid = threadIdx.x;
    const int n0  = blockIdx.x * 64;       // 0..2047
    const int m0  = blockIdx.y * 128;
    const int gate = n0 >> 9;
    const int nc0  = n0 & 511;
    const float* W    = (gate == 0) ? W0 : (gate == 1) ? W1 : (gate == 2) ? W2 : W3;
    const float* bias = (gate == 0) ? b0 : (gate == 1) ? b1 : (gate == 2) ? b2 : b3;

    const int warp = tid >> 5;
    const int wr = warp & 3;               // 4 warps along M (32 rows each)
    const int wc = warp >> 2;              // 2 warps along N (32 cols each)

    wmma::fragment<wmma::accumulator, 16, 16, 8, float> c[2][2];
    #pragma unroll
    for (int i = 0; i < 2; i++)
        #pragma unroll
        for (int j = 0; j < 2; j++) wmma::fill_fragment(c[i][j], 0.f);

    for (int k0 = 0; k0 < 512; k0 += 16) {
        #pragma unroll
        for (int i = tid; i < 128 * 16; i += 256) {
            int r = i >> 4, cc = i & 15;
            float v  = A[(size_t)(m0 + r) * 512 + k0 + cc];
            float hi = to_tf32(v);
            sAhi[i] = hi;
            sAlo[i] = to_tf32(v - hi);
        }
        #pragma unroll
        for (int i = tid; i < 16 * 64; i += 256) {
            int r = i >> 6, cc = i & 63;
            float v  = W[(size_t)(krow_off + k0 + r) * 512 + nc0 + cc];
            float hi = to_tf32(v);
            sBhi[i] = hi;
            sBlo[i] = to_tf32(v - hi);
        }
        __syncthreads();

        #pragma unroll
        for (int kk = 0; kk < 16; kk += 8) {
            wmma::fragment<wmma::matrix_a, 16, 16, 8, wmma::precision::tf32, wmma::row_major> ahi[2], alo[2];
            wmma::fragment<wmma::matrix_b, 16, 16, 8, wmma::precision::tf32, wmma::row_major> bhi[2], blo[2];
            #pragma unroll
            for (int i = 0; i < 2; i++) {
                wmma::load_matrix_sync(ahi[i], sAhi + (wr * 32 + i * 16) * 16 + kk, 16);
                wmma::load_matrix_sync(alo[i], sAlo + (wr * 32 + i * 16) * 16 + kk, 16);
            }
            #pragma unroll
            for (int j = 0; j < 2; j++) {
                wmma::load_matrix_sync(bhi[j], sBhi + kk * 64 + wc * 32 + j * 16, 64);
                wmma::load_matrix_sync(blo[j], sBlo + kk * 64 + wc * 32 + j * 16, 64);
            }
            #pragma unroll
            for (int i = 0; i < 2; i++)
                #pragma unroll
                for (int j = 0; j < 2; j++) {
                    wmma::mma_sync(c[i][j], ahi[i], bhi[j], c[i][j]);  // hi*hi
                    wmma::mma_sync(c[i][j], ahi[i], blo[j], c[i][j]);  // hi*lo
                    wmma::mma_sync(c[i][j], alo[i], bhi[j], c[i][j]);  // lo*hi
                }
        }
        __syncthreads();
    }

    float* sC = pool;                      // 128 x 64
    #pragma unroll
    for (int i = 0; i < 2; i++)
        #pragma unroll
        for (int j = 0; j < 2; j++)
            wmma::store_matrix_sync(sC + (wr * 32 + i * 16) * 64 + wc * 32 + j * 16,
                                    c[i][j], 64, wmma::mem_row_major);
    __syncthreads();

    for (int i = tid; i < 128 * 64; i += 256) {
        int r = i >> 6, cc = i & 63;
        float v = sC[i];
        size_t g = (size_t)(m0 + r) * NTOT + n0 + cc;
        v += accumulate ? C[g] : bias[nc0 + cc];
        C[g] = v;
    }
}

// ---------------- precompute XQ = inputs @ Wq[0:512] + bq -------------------
// one warp per sample row
__global__ void __launch_bounds__(512) xq_kernel(
    const float* __restrict__ inputs, const float* __restrict__ Wq,
    const float* __restrict__ bq)
{
    int gw   = blockIdx.x * (blockDim.x >> 5) + (threadIdx.x >> 5);
    int lane = threadIdx.x & 31;
    if (gw >= T_STEPS * BATCH) return;
    const float* x = inputs + (size_t)gw * DIM;
    float acc[NQV];
    #pragma unroll
    for (int q = 0; q < NQV; q++) acc[q] = 0.f;
    for (int k = lane; k < DIM; k += 32) {
        float xv = x[k];
        const float* wrow = Wq + (size_t)k * NQV;
        #pragma unroll
        for (int q = 0; q < NQV; q++) acc[q] += xv * wrow[q];
    }
    #pragma unroll
    for (int q = 0; q < NQV; q++) {
        float v = acc[q];
        #pragma unroll
        for (int off = 16; off; off >>= 1) v += __shfl_xor_sync(0xffffffffu, v, off);
        acc[q] = v;
    }
    if (lane == 0) {
        #pragma unroll
        for (int q = 0; q < NQV; q++) g_XQ[(size_t)gw * NQV + q] = acc[q] + bq[q];
    }
}

// ---------------- per-step: q path + gate combine + LSTM update -------------
// grid: BATCH blocks, HID threads. Reads g_hx (prev), writes g_hx/g_cx/out[t].
__global__ void __launch_bounds__(512) update_kernel(
    const float* __restrict__ XPt, const float* __restrict__ XQt,
    const float* __restrict__ Wq,  const float* __restrict__ Wqh,
    const float* __restrict__ bqh,
    const float* __restrict__ th_f, const float* __restrict__ th_i,
    const float* __restrict__ th_u, const float* __restrict__ th_o,
    float* __restrict__ out_t, float* __restrict__ out_h, float* __restrict__ out_c,
    int is_last)
{
    const int b = blockIdx.x;
    const int n = threadIdx.x;
    __shared__ float hx_sm[HID];
    __shared__ float qin_sm[NQV];
    __shared__ float z_sm[4][NQV];

    hx_sm[n] = g_hx[b * HID + n];
    __syncthreads();

    // q_in = XQt[b] + hx @ Wq[512:1024]   (warp 0: 4 lanes per output q)
    if (n < 32) {
        int q = n >> 2, part = n & 3;
        float acc = 0.f;
        int k0 = part * 128;
        #pragma unroll 8
        for (int k = k0; k < k0 + 128; ++k)
            acc += hx_sm[k] * Wq[(size_t)(DIM + k) * NQV + q];
        acc += __shfl_down_sync(0xffffffffu, acc, 2);
        acc += __shfl_down_sync(0xffffffffu, acc, 1);
        if (part == 0) qin_sm[q] = acc + XQt[b * NQV + q];
    }
    __syncthreads();

    // qlayer: cumprod(cos(q_in + theta)) for 4 thetas
    if (n < 4) {
        const float* th = (n == 0) ? th_f : (n == 1) ? th_i : (n == 2) ? th_u : th_o;
        float run = 1.f;
        #pragma unroll
        for (int j = 0; j < NQV; ++j) {
            run *= cosf(qin_sm[j] + th[j]);
            z_sm[n][j] = run;
        }
    }
    __syncthreads();

    // q-gate projections (8->512), shared Wqh column reused across 4 gates
    float bq_ = bqh[n];
    float a0 = bq_, a1 = bq_, a2 = bq_, a3 = bq_;
    #pragma unroll
    for (int q = 0; q < NQV; ++q) {
        float w = Wqh[q * HID + n];
        a0 += z_sm[0][q] * w;
        a1 += z_sm[1][q] * w;
        a2 += z_sm[2][q] * w;
        a3 += z_sm[3][q] * w;
    }

    const float* xp = XPt + (size_t)b * NTOT;   // [f | i | u | o] preactivations (full: x+h+bias)
    float pf = xp[n], pi = xp[HID + n], pu = xp[2 * HID + n], po = xp[3 * HID + n];

    float f  = ALPHA_F * sigm(pf)  + ALPHB_F * sigm(a0);
    float ii = ALPHA_F * sigm(pi)  + ALPHB_F * sigm(a1);
    float gg = ALPHA_F * tanhf(pu) + ALPHB_F * tanhf(a2);
    float oo = ALPHA_F * sigm(po)  + ALPHB_F * sigm(a3);

    int idx = b * HID + n;
    float c_new = f * g_cx[idx] + ii * gg;
    float h_new = oo * tanhf(c_new);
    g_cx[idx] = c_new;
    g_hx[idx] = h_new;
    out_t[idx] = h_new;
    if (is_last) { out_h[idx] = h_new; out_c[idx] = c_new; }
}

// ---------------- launch ----------------------------------------------------
extern "C" void kernel_launch(void* const* d_in, const int* in_sizes, int n_in,
                              void* d_out, int out_size)
{
    const float* inputs = (const float*)d_in[0];
    const float* Wf = (const float*)d_in[1];
    const float* bf = (const float*)d_in[2];
    const float* Wi = (const float*)d_in[3];
    const float* bi = (const float*)d_in[4];
    const float* Wu = (const float*)d_in[5];
    const float* bu = (const float*)d_in[6];
    const float* Wo = (const float*)d_in[7];
    const float* bo = (const float*)d_in[8];
    const float* Wq = (const float*)d_in[9];
    const float* bq = (const float*)d_in[10];
    const float* Wqh = (const float*)d_in[11];
    const float* bqh = (const float*)d_in[12];
    const float* th_f = (const float*)d_in[13];
    const float* th_i = (const float*)d_in[14];
    const float* th_u = (const float*)d_in[15];
    const float* th_o = (const float*)d_in[16];
    float* out = (float*)d_out;

    float *XP, *XQ, *hx;
    cudaGetSymbolAddress((void**)&XP, g_XP);
    cudaGetSymbolAddress((void**)&XQ, g_XQ);
    cudaGetSymbolAddress((void**)&hx, g_hx);
    (void)XQ;

    zero_state<<<(BATCH * HID + 511) / 512, 512>>>();

    // x-part of all gate preactivations for all T (parallel): XP = X @ Wx + b
    gemm3tf32<<<dim3(NTOT / 64, (T_STEPS * BATCH) / 128), 256>>>(
        inputs, 0, Wf, Wi, Wu, Wo, bf, bi, bu, bo, XP, 0);

    // x-part of q_in for all T
    xq_kernel<<<(T_STEPS * BATCH) / 16, 512>>>(inputs, Wq, bq);

    const size_t outT = (size_t)T_STEPS * BATCH * HID;
    int tails = (out_size >= (int)(outT + 2 * BATCH * HID)) ? 1 : 0;

    for (int t = 0; t < T_STEPS; ++t) {
        float* XPt = XP + (size_t)t * BATCH * NTOT;
        // XP[t] += hx @ Wh  (recurrent half, rows 512..1023 of W)
        gemm3tf32<<<dim3(NTOT / 64, BATCH / 128), 256>>>(
            hx, 512, Wf, Wi, Wu, Wo, bf, bi, bu, bo, XPt, 1);
        update_kernel<<<BATCH, HID>>>(
            XPt, XQ + (size_t)t * BATCH * NQV,
            Wq, Wqh, bqh, th_f, th_i, th_u, th_o,
            out + (size_t)t * BATCH * HID,
            out + outT, out + outT + BATCH * HID,
            (t == T_STEPS - 1) ? tails : 0);
    }
}

// round 2
// speedup vs baseline: 1.4944x; 1.4944x over previous
#include <cuda_runtime.h>
#include <mma.h>
#include <cstdint>
#include <cstdio>

using namespace nvcuda;

#define T_STEPS 256
#define BATCH   512
#define DIM     512
#define HID     512
#define NQV     8
#define NTOT    2048   // 4*HID
#define ALPHA_F 0.7f
#define ALPHB_F 0.3f

// ---------------- scratch (device globals; no allocations allowed) ----------
__device__ float g_XP[(size_t)T_STEPS * BATCH * NTOT];   // 1.07 GB: x-part preactivations + bias
__device__ float g_XQ[(size_t)T_STEPS * BATCH * NQV];    // 4 MB:  x-part of q_in + bias
__device__ float g_hx[BATCH * HID];
__device__ float g_cx[BATCH * HID];

__device__ __forceinline__ float to_tf32(float x) {
    float r; asm("cvt.rna.tf32.f32 %0, %1;" : "=f"(r) : "f"(x)); return r;
}
__device__ __forceinline__ float sigm(float x) { return 1.f / (1.f + expf(-x)); }

// ---------------- zero recurrent state (graph-replay determinism) -----------
__global__ void zero_state() {
    int i = blockIdx.x * blockDim.x + threadIdx.x;
    if (i < BATCH * HID) { g_hx[i] = 0.f; g_cx[i] = 0.f; }
}

// ---------------- 3xTF32 GEMM: C[M x 2048] (+)= A[M x 512] * W_gate + bias --
// A row-major, lda=512. W per gate: (1024 x 512) row-major; rows [krow_off, krow_off+512).
// accumulate=0: C = A*W + bias ; accumulate=1: C += A*W
__global__ void __launch_bounds__(256) gemm3tf32(
    const float* __restrict__ A, int krow_off,
    const float* __restrict__ W0, const float* __restrict__ W1,
    const float* __restrict__ W2, const float* __restrict__ W3,
    const float* __restrict__ b0, const float* __restrict__ b1,
    const float* __restrict__ b2, const float* __restrict__ b3,
    float* __restrict__ C, int accumulate)
{
    __shared__ float pool[8192];           // 32 KB, aliased: tiles then C-tile
    float* sAhi = pool;                    // 128 x 16
    float* sAlo = pool + 2048;
    float* sBhi = pool + 4096;             // 16 x 64
    float* sBlo = pool + 5120;

    const int tid = threadIdx.x;
    const int n0  = blockIdx.x * 64;       // 0..2047
    const int m0  = blockIdx.y * 128;
    const int gate = n0 >> 9;
    const int nc0  = n0 & 511;
    const float* W    = (gate == 0) ? W0 : (gate == 1) ? W1 : (gate == 2) ? W2 : W3;
    const float* bias = (gate == 0) ? b0 : (gate == 1) ? b1 : (gate == 2) ? b2 : b3;

    const int warp = tid >> 5;
    const int wr = warp & 3;               // 4 warps along M (32 rows each)
    const int wc = warp >> 2;              // 2 warps along N (32 cols each)

    wmma::fragment<wmma::accumulator, 16, 16, 8, float> c[2][2];
    #pragma unroll
    for (int i = 0; i < 2; i++)
        #pragma unroll
        for (int j = 0; j < 2; j++) wmma::fill_fragment(c[i][j], 0.f);

    for (int k0 = 0; k0 < 512; k0 += 16) {
        #pragma unroll
        for (int i = tid; i < 128 * 16; i += 256) {
            int r = i >> 4, cc = i & 15;
            float v  = A[(size_t)(m0 + r) * 512 + k0 + cc];
            float hi = to_tf32(v);
            sAhi[i] = hi;
            sAlo[i] = to_tf32(v - hi);
        }
        #pragma unroll
        for (int i = tid; i < 16 * 64; i += 256) {
            int r = i >> 6, cc = i & 63;
            float v  = W[(size_t)(krow_off + k0 + r) * 512 + nc0 + cc];
            float hi = to_tf32(v);
            sBhi[i] = hi;
            sBlo[i] = to_tf32(v - hi);
        }
        __syncthreads();

        #pragma unroll
        for (int kk = 0; kk < 16; kk += 8) {
            wmma::fragment<wmma::matrix_a, 16, 16, 8, wmma::precision::tf32, wmma::row_major> ahi[2], alo[2];
            wmma::fragment<wmma::matrix_b, 16, 16, 8, wmma::precision::tf32, wmma::row_major> bhi[2], blo[2];
            #pragma unroll
            for (int i = 0; i < 2; i++) {
                wmma::load_matrix_sync(ahi[i], sAhi + (wr * 32 + i * 16) * 16 + kk, 16);
                wmma::load_matrix_sync(alo[i], sAlo + (wr * 32 + i * 16) * 16 + kk, 16);
            }
            #pragma unroll
            for (int j = 0; j < 2; j++) {
                wmma::load_matrix_sync(bhi[j], sBhi + kk * 64 + wc * 32 + j * 16, 64);
                wmma::load_matrix_sync(blo[j], sBlo + kk * 64 + wc * 32 + j * 16, 64);
            }
            #pragma unroll
            for (int i = 0; i < 2; i++)
                #pragma unroll
                for (int j = 0; j < 2; j++) {
                    wmma::mma_sync(c[i][j], ahi[i], bhi[j], c[i][j]);  // hi*hi
                    wmma::mma_sync(c[i][j], ahi[i], blo[j], c[i][j]);  // hi*lo
                    wmma::mma_sync(c[i][j], alo[i], bhi[j], c[i][j]);  // lo*hi
                }
        }
        __syncthreads();
    }

    float* sC = pool;                      // 128 x 64
    #pragma unroll
    for (int i = 0; i < 2; i++)
        #pragma unroll
        for (int j = 0; j < 2; j++)
            wmma::store_matrix_sync(sC + (wr * 32 + i * 16) * 64 + wc * 32 + j * 16,
                                    c[i][j], 64, wmma::mem_row_major);
    __syncthreads();

    for (int i = tid; i < 128 * 64; i += 256) {
        int r = i >> 6, cc = i & 63;
        float v = sC[i];
        size_t g = (size_t)(m0 + r) * NTOT + n0 + cc;
        v += accumulate ? C[g] : bias[nc0 + cc];
        C[g] = v;
    }
}

// ---------------- precompute XQ = inputs @ Wq[0:512] + bq -------------------
// one warp per sample row
__global__ void __launch_bounds__(512) xq_kernel(
    const float* __restrict__ inputs, const float* __restrict__ Wq,
    const float* __restrict__ bq)
{
    int gw   = blockIdx.x * (blockDim.x >> 5) + (threadIdx.x >> 5);
    int lane = threadIdx.x & 31;
    if (gw >= T_STEPS * BATCH) return;
    const float* x = inputs + (size_t)gw * DIM;
    float acc[NQV];
    #pragma unroll
    for (int q = 0; q < NQV; q++) acc[q] = 0.f;
    for (int k = lane; k < DIM; k += 32) {
        float xv = x[k];
        const float* wrow = Wq + (size_t)k * NQV;
        #pragma unroll
        for (int q = 0; q < NQV; q++) acc[q] += xv * wrow[q];
    }
    #pragma unroll
    for (int q = 0; q < NQV; q++) {
        float v = acc[q];
        #pragma unroll
        for (int off = 16; off; off >>= 1) v += __shfl_xor_sync(0xffffffffu, v, off);
        acc[q] = v;
    }
    if (lane == 0) {
        #pragma unroll
        for (int q = 0; q < NQV; q++) g_XQ[(size_t)gw * NQV + q] = acc[q] + bq[q];
    }
}

// ---------------- per-step: q path + gate combine + LSTM update -------------
// grid: BATCH blocks, HID threads. Reads g_hx (prev), writes g_hx/g_cx/out[t].
__global__ void __launch_bounds__(512) update_kernel(
    const float* __restrict__ XPt, const float* __restrict__ XQt,
    const float* __restrict__ Wq,  const float* __restrict__ Wqh,
    const float* __restrict__ bqh,
    const float* __restrict__ th_f, const float* __restrict__ th_i,
    const float* __restrict__ th_u, const float* __restrict__ th_o,
    float* __restrict__ out_t, float* __restrict__ out_h, float* __restrict__ out_c,
    int is_last)
{
    const int b = blockIdx.x;
    const int n = threadIdx.x;
    __shared__ float hx_sm[HID];
    __shared__ float qin_sm[NQV];
    __shared__ float z_sm[4][NQV];

    hx_sm[n] = g_hx[b * HID + n];
    __syncthreads();

    // q_in = XQt[b] + hx @ Wq[512:1024]   (warp 0: 4 lanes per output q)
    if (n < 32) {
        int q = n >> 2, part = n & 3;
        float acc = 0.f;
        int k0 = part * 128;
        #pragma unroll 8
        for (int k = k0; k < k0 + 128; ++k)
            acc += hx_sm[k] * Wq[(size_t)(DIM + k) * NQV + q];
        acc += __shfl_down_sync(0xffffffffu, acc, 2);
        acc += __shfl_down_sync(0xffffffffu, acc, 1);
        if (part == 0) qin_sm[q] = acc + XQt[b * NQV + q];
    }
    __syncthreads();

    // qlayer: cumprod(cos(q_in + theta)) for 4 thetas
    if (n < 4) {
        const float* th = (n == 0) ? th_f : (n == 1) ? th_i : (n == 2) ? th_u : th_o;
        float run = 1.f;
        #pragma unroll
        for (int j = 0; j < NQV; ++j) {
            run *= cosf(qin_sm[j] + th[j]);
            z_sm[n][j] = run;
        }
    }
    __syncthreads();

    // q-gate projections (8->512), shared Wqh column reused across 4 gates
    float bq_ = bqh[n];
    float a0 = bq_, a1 = bq_, a2 = bq_, a3 = bq_;
    #pragma unroll
    for (int q = 0; q < NQV; ++q) {
        float w = Wqh[q * HID + n];
        a0 += z_sm[0][q] * w;
        a1 += z_sm[1][q] * w;
        a2 += z_sm[2][q] * w;
        a3 += z_sm[3][q] * w;
    }

    const float* xp = XPt + (size_t)b * NTOT;   // [f | i | u | o] preactivations (full: x+h+bias)
    float pf = xp[n], pi = xp[HID + n], pu = xp[2 * HID + n], po = xp[3 * HID + n];

    float f  = ALPHA_F * sigm(pf)  + ALPHB_F * sigm(a0);
    float ii = ALPHA_F * sigm(pi)  + ALPHB_F * sigm(a1);
    float gg = ALPHA_F * tanhf(pu) + ALPHB_F * tanhf(a2);
    float oo = ALPHA_F * sigm(po)  + ALPHB_F * sigm(a3);

    int idx = b * HID + n;
    float c_new = f * g_cx[idx] + ii * gg;
    float h_new = oo * tanhf(c_new);
    g_cx[idx] = c_new;
    g_hx[idx] = h_new;
    out_t[idx] = h_new;
    if (is_last) { out_h[idx] = h_new; out_c[idx] = c_new; }
}

// ---------------- launch ----------------------------------------------------
extern "C" void kernel_launch(void* const* d_in, const int* in_sizes, int n_in,
                              void* d_out, int out_size)
{
    const float* inputs = (const float*)d_in[0];
    const float* Wf = (const float*)d_in[1];
    const float* bf = (const float*)d_in[2];
    const float* Wi = (const float*)d_in[3];
    const float* bi = (const float*)d_in[4];
    const float* Wu = (const float*)d_in[5];
    const float* bu = (const float*)d_in[6];
    const float* Wo = (const float*)d_in[7];
    const float* bo = (const float*)d_in[8];
    const float* Wq = (const float*)d_in[9];
    const float* bq = (const float*)d_in[10];
    const float* Wqh = (const float*)d_in[11];
    const float* bqh = (const float*)d_in[12];
    const float* th_f = (const float*)d_in[13];
    const float* th_i = (const float*)d_in[14];
    const float* th_u = (const float*)d_in[15];
    const float* th_o = (const float*)d_in[16];
    float* out = (float*)d_out;

    float *XP, *XQ, *hx;
    cudaGetSymbolAddress((void**)&XP, g_XP);
    cudaGetSymbolAddress((void**)&XQ, g_XQ);
    cudaGetSymbolAddress((void**)&hx, g_hx);
    (void)XQ;

    zero_state<<<(BATCH * HID + 511) / 512, 512>>>();

    // x-part of all gate preactivations for all T (parallel): XP = X @ Wx + b
    gemm3tf32<<<dim3(NTOT / 64, (T_STEPS * BATCH) / 128), 256>>>(
        inputs, 0, Wf, Wi, Wu, Wo, bf, bi, bu, bo, XP, 0);

    // x-part of q_in for all T
    xq_kernel<<<(T_STEPS * BATCH) / 16, 512>>>(inputs, Wq, bq);

    const size_t outT = (size_t)T_STEPS * BATCH * HID;
    int tails = (out_size >= (int)(outT + 2 * BATCH * HID)) ? 1 : 0;

    for (int t = 0; t < T_STEPS; ++t) {
        float* XPt = XP + (size_t)t * BATCH * NTOT;
        // XP[t] += hx @ Wh  (recurrent half, rows 512..1023 of W)
        gemm3tf32<<<dim3(NTOT / 64, BATCH / 128), 256>>>(
            hx, 512, Wf, Wi, Wu, Wo, bf, bi, bu, bo, XPt, 1);
        update_kernel<<<BATCH, HID>>>(
            XPt, XQ + (size_t)t * BATCH * NQV,
            Wq, Wqh, bqh, th_f, th_i, th_u, th_o,
            out + (size_t)t * BATCH * HID,
            out + outT, out + outT + BATCH * HID,
            (t == T_STEPS - 1) ? tails : 0);
    }
}

// round 3
// speedup vs baseline: 1.5706x; 1.0510x over previous
#include <cuda_runtime.h>
#include <cuda_bf16.h>
#include <mma.h>
#include <cstdint>

using namespace nvcuda;
typedef __nv_bfloat16 bf16;

#define T_STEPS 256
#define BATCH   512
#define DIM     512
#define HID     512
#define NQV     8
#define NTOT    2048
#define MROWS   (T_STEPS*BATCH)
#define ALPHA_F 0.7f
#define ALPHB_F 0.3f
#define NBLOCKS 128

// ---------------- device-global scratch (no allocations allowed) ------------
__device__ float g_XP[(size_t)MROWS * NTOT];      // x-part preacts (interleaved cols)
__device__ float g_XQ[(size_t)MROWS * NQV];       // x-part of q_in + bq
__device__ bf16  g_Xhi[(size_t)MROWS * DIM];
__device__ bf16  g_Xlo[(size_t)MROWS * DIM];
__device__ bf16  g_WxHi[512 * NTOT];              // interleaved: [k][4j+g] = Wg[k][j]
__device__ bf16  g_WxLo[512 * NTOT];
__device__ bf16  g_WhHi[512 * NTOT];              // [k][4j+g] = Wg[512+k][j]
__device__ bf16  g_WhLo[512 * NTOT];
__device__ float g_biasI[NTOT];                   // [4j+g] = b_g[j]
__device__ bf16  g_hHi[2][BATCH * HID];           // double-buffered h (split)
__device__ bf16  g_hLo[2][BATCH * HID];
__device__ unsigned g_arrive;
__device__ volatile unsigned g_gen;

__device__ __forceinline__ float sigm(float x) { return 1.f / (1.f + expf(-x)); }

__device__ __forceinline__ void cpa16(void* s, const void* g) {
    unsigned sa = (unsigned)__cvta_generic_to_shared(s);
    asm volatile("cp.async.cg.shared.global [%0], [%1], 16;\n" :: "r"(sa), "l"(g));
}
__device__ __forceinline__ void cp_commit() { asm volatile("cp.async.commit_group;\n" ::: "memory"); }
__device__ __forceinline__ void cp_wait1()  { asm volatile("cp.async.wait_group 1;\n" ::: "memory"); }
__device__ __forceinline__ void cp_wait0()  { asm volatile("cp.async.wait_group 0;\n" ::: "memory"); }

// ---------------- init: zero h buffers + barrier state -----------------------
__global__ void zero_state() {
    int i = blockIdx.x * blockDim.x + threadIdx.x;
    if (i < 2 * BATCH * HID) {
        ((bf16*)g_hHi)[i] = __float2bfloat16(0.f);
        ((bf16*)g_hLo)[i] = __float2bfloat16(0.f);
    }
    if (i == 0) { g_arrive = 0; g_gen = 0; }
}

// ---------------- split inputs into bf16 hi/lo --------------------------------
__global__ void cvt_x(const float* __restrict__ x) {
    size_t i = (size_t)blockIdx.x * blockDim.x + threadIdx.x;
    if (i >= (size_t)MROWS * DIM) return;
    float v = x[i];
    bf16 h = __float2bfloat16_rn(v);
    g_Xhi[i] = h;
    g_Xlo[i] = __float2bfloat16_rn(v - __bfloat162float(h));
}

// ---------------- build interleaved split weights + bias ----------------------
__global__ void cvt_w(const float* __restrict__ w0, const float* __restrict__ w1,
                      const float* __restrict__ w2, const float* __restrict__ w3,
                      const float* __restrict__ b0, const float* __restrict__ b1,
                      const float* __restrict__ b2, const float* __restrict__ b3) {
    int i = blockIdx.x * blockDim.x + threadIdx.x;
    if (i >= 512 * NTOT) return;
    int k = i >> 11, np = i & (NTOT - 1);
    int j = np >> 2, g = np & 3;
    const float* W = (g == 0) ? w0 : (g == 1) ? w1 : (g == 2) ? w2 : w3;
    float vx = W[(size_t)k * 512 + j];
    float vh = W[(size_t)(512 + k) * 512 + j];
    bf16 hx = __float2bfloat16_rn(vx);
    g_WxHi[i] = hx;
    g_WxLo[i] = __float2bfloat16_rn(vx - __bfloat162float(hx));
    bf16 hh = __float2bfloat16_rn(vh);
    g_WhHi[i] = hh;
    g_WhLo[i] = __float2bfloat16_rn(vh - __bfloat162float(hh));
    if (k == 0) {
        const float* B = (g == 0) ? b0 : (g == 1) ? b1 : (g == 2) ? b2 : b3;
        g_biasI[np] = B[j];
    }
}

// ---------------- XQ = inputs @ Wq[0:512] + bq (warp per row) -----------------
__global__ void __launch_bounds__(512) xq_kernel(
    const float* __restrict__ inputs, const float* __restrict__ Wq,
    const float* __restrict__ bq)
{
    int gw   = blockIdx.x * (blockDim.x >> 5) + (threadIdx.x >> 5);
    int lane = threadIdx.x & 31;
    if (gw >= MROWS) return;
    const float* x = inputs + (size_t)gw * DIM;
    float acc[NQV];
    #pragma unroll
    for (int q = 0; q < NQV; q++) acc[q] = 0.f;
    for (int k = lane; k < DIM; k += 32) {
        float xv = x[k];
        const float* wrow = Wq + (size_t)k * NQV;
        #pragma unroll
        for (int q = 0; q < NQV; q++) acc[q] += xv * wrow[q];
    }
    #pragma unroll
    for (int q = 0; q < NQV; q++) {
        float v = acc[q];
        #pragma unroll
        for (int off = 16; off; off >>= 1) v += __shfl_xor_sync(0xffffffffu, v, off);
        acc[q] = v;
    }
    if (lane == 0) {
        #pragma unroll
        for (int q = 0; q < NQV; q++) g_XQ[(size_t)gw * NQV + q] = acc[q] + bq[q];
    }
}

// ---------------- precompute GEMM: XP = Xsplit @ Wx' (bf16x3, no bias) --------
// grid (16 Ntiles, 1024 Mtiles), 256 threads, 64KB dyn smem, cp.async 2-stage
#define GX_BUF 32768
__global__ void __launch_bounds__(256, 2) gemm_x()
{
    extern __shared__ char smem[];
    const int tid = threadIdx.x;
    const int n0 = blockIdx.x * 128;
    const size_t m0 = (size_t)blockIdx.y * 128;

    const int warp = tid >> 5;
    const int wr = warp & 3;      // M: 4 warps x 32 rows
    const int wc = warp >> 2;     // N: 2 warps x 64 cols

    wmma::fragment<wmma::accumulator, 16, 16, 16, float> acc[2][4];
    #pragma unroll
    for (int i = 0; i < 2; i++)
        #pragma unroll
        for (int j = 0; j < 4; j++) wmma::fill_fragment(acc[i][j], 0.f);

    auto ld_chunk = [&](int kc, int buf) {
        char* base = smem + buf * GX_BUF;
        #pragma unroll
        for (int it = 0; it < 2; ++it) {            // A: 128x32 hi+lo
            int x = tid * 2 + it;                   // 0..511
            int r = x >> 2, c4 = x & 3;
            cpa16(base + r * 64 + c4 * 16,          g_Xhi + (m0 + r) * DIM + kc * 32 + c4 * 8);
            cpa16(base + 8192 + r * 64 + c4 * 16,   g_Xlo + (m0 + r) * DIM + kc * 32 + c4 * 8);
        }
        #pragma unroll
        for (int it = 0; it < 2; ++it) {            // B: 32x128 hi+lo
            int x = tid * 2 + it;
            int r = x >> 4, c16 = x & 15;
            cpa16(base + 16384 + r * 256 + c16 * 16, g_WxHi + (size_t)(kc * 32 + r) * NTOT + n0 + c16 * 8);
            cpa16(base + 24576 + r * 256 + c16 * 16, g_WxLo + (size_t)(kc * 32 + r) * NTOT + n0 + c16 * 8);
        }
    };

    ld_chunk(0, 0); cp_commit();
    for (int kc = 0; kc < 16; ++kc) {
        if (kc < 15) { ld_chunk(kc + 1, (kc + 1) & 1); cp_commit(); cp_wait1(); }
        else cp_wait0();
        __syncthreads();
        char* base = smem + (kc & 1) * GX_BUF;
        const bf16* Ahi = (const bf16*)base;
        const bf16* Alo = (const bf16*)(base + 8192);
        const bf16* Bhi = (const bf16*)(base + 16384);
        const bf16* Blo = (const bf16*)(base + 24576);
        #pragma unroll
        for (int ks = 0; ks < 2; ++ks) {
            wmma::fragment<wmma::matrix_a, 16, 16, 16, bf16, wmma::row_major> ahi[2], alo[2];
            wmma::fragment<wmma::matrix_b, 16, 16, 16, bf16, wmma::row_major> bhi[4], blo[4];
            #pragma unroll
            for (int i = 0; i < 2; i++) {
                wmma::load_matrix_sync(ahi[i], Ahi + (wr * 32 + i * 16) * 32 + ks * 16, 32);
                wmma::load_matrix_sync(alo[i], Alo + (wr * 32 + i * 16) * 32 + ks * 16, 32);
            }
            #pragma unroll
            for (int j = 0; j < 4; j++) {
                wmma::load_matrix_sync(bhi[j], Bhi + (ks * 16) * 128 + wc * 64 + j * 16, 128);
                wmma::load_matrix_sync(blo[j], Blo + (ks * 16) * 128 + wc * 64 + j * 16, 128);
            }
            #pragma unroll
            for (int i = 0; i < 2; i++)
                #pragma unroll
                for (int j = 0; j < 4; j++) {
                    wmma::mma_sync(acc[i][j], ahi[i], bhi[j], acc[i][j]);
                    wmma::mma_sync(acc[i][j], ahi[i], blo[j], acc[i][j]);
                    wmma::mma_sync(acc[i][j], alo[i], bhi[j], acc[i][j]);
                }
        }
        __syncthreads();
    }
    #pragma unroll
    for (int i = 0; i < 2; i++)
        #pragma unroll
        for (int j = 0; j < 4; j++) {
            size_t row0 = m0 + wr * 32 + i * 16;
            int    col0 = n0 + wc * 64 + j * 16;
            wmma::store_matrix_sync(g_XP + row0 * NTOT + col0, acc[i][j], NTOT, wmma::mem_row_major);
        }
}

// ---------------- persistent recurrent kernel --------------------------------
// smem map (bytes):
#define PS_W_HI  0        // 512x64 bf16 = 65536
#define PS_W_LO  65536
#define PS_A     131072   // 2 bufs x (hi 128x72 + lo 128x72) bf16 = 2*36864
#define PS_ABUF  36864
#define PS_WQH   204800   // 512x8 f32 = 16384
#define PS_BIAS  221184   // 64 f32
#define PS_WQHS  221440   // 8x16 f32
#define PS_BQH   221952   // 16 f32
#define PS_TH    222016   // 32 f32
#define PS_TOTAL 222144
// epilogue alias over PS_A: sP 128x64 f32 @+0 (32768), sZ 128x32 f32 @+32768, sQ 128x2x8 f32 @+49152

__device__ __forceinline__ void grid_barrier() {
    __syncthreads();
    if (threadIdx.x == 0) {
        __threadfence();
        unsigned gen = g_gen;
        if (atomicAdd(&g_arrive, 1u) == NBLOCKS - 1) {
            g_arrive = 0;
            __threadfence();
            g_gen = gen + 1;
        } else {
            while (g_gen == gen) { }
            __threadfence();
        }
    }
    __syncthreads();
}

__global__ void __launch_bounds__(256, 1) qlstm_persistent(
    const float* __restrict__ Wq,  const float* __restrict__ Wqh,
    const float* __restrict__ bqh,
    const float* __restrict__ thf, const float* __restrict__ thi,
    const float* __restrict__ thu, const float* __restrict__ tho,
    float* __restrict__ out, int tails)
{
    extern __shared__ char smem[];
    const int tid = threadIdx.x;
    const int bx = blockIdx.x;           // 0..127
    const int mt = bx >> 5, nt = bx & 31;
    const int m0 = mt * 128;             // batch-row base
    const int nc0 = nt * 64;             // interleaved col base
    const int warp = tid >> 5;
    const int wr = warp & 3, wc = warp >> 2;

    bf16* sWhi = (bf16*)(smem + PS_W_HI);
    bf16* sWlo = (bf16*)(smem + PS_W_LO);
    for (int i = tid; i < 512 * 64; i += 256) {
        int k = i >> 6, nl = i & 63;
        sWhi[i] = g_WhHi[(size_t)k * NTOT + nc0 + nl];
        sWlo[i] = g_WhLo[(size_t)k * NTOT + nc0 + nl];
    }
    float* sWqH = (float*)(smem + PS_WQH);
    for (int i = tid; i < 512 * 8; i += 256)
        sWqH[i] = Wq[(size_t)(512 + (i >> 3)) * NQV + (i & 7)];
    float* sBias = (float*)(smem + PS_BIAS);
    if (tid < 64) sBias[tid] = g_biasI[nc0 + tid];
    float* sWqhS = (float*)(smem + PS_WQHS);
    if (tid < 128) sWqhS[tid] = Wqh[(size_t)(tid >> 4) * HID + nt * 16 + (tid & 15)];
    float* sBqh = (float*)(smem + PS_BQH);
    if (tid < 16) sBqh[tid] = bqh[nt * 16 + tid];
    float* sTh = (float*)(smem + PS_TH);
    if (tid < 32) {
        int g = tid >> 3, q = tid & 7;
        sTh[tid] = (g == 0) ? thf[q] : (g == 1) ? thi[q] : (g == 2) ? thu[q] : tho[q];
    }
    float c_state[8];
    #pragma unroll
    for (int i = 0; i < 8; i++) c_state[i] = 0.f;
    __syncthreads();

    const int qr = tid >> 1;            // row for q-accum (2 threads/row)
    const int qh = tid & 1;             // k-half within chunk

    for (int t = 0; t < T_STEPS; ++t) {
        const int rbuf = t & 1, wbuf = rbuf ^ 1;
        const bf16* hHi = g_hHi[rbuf];
        const bf16* hLo = g_hLo[rbuf];

        wmma::fragment<wmma::accumulator, 16, 16, 16, float> acc[2][2];
        #pragma unroll
        for (int i = 0; i < 2; i++)
            #pragma unroll
            for (int j = 0; j < 2; j++) wmma::fill_fragment(acc[i][j], 0.f);

        float qacc[NQV];
        #pragma unroll
        for (int q = 0; q < NQV; q++) qacc[q] = 0.f;

        auto ldA = [&](int kc, int buf) {
            char* base = smem + PS_A + buf * PS_ABUF;
            #pragma unroll
            for (int it = 0; it < 4; ++it) {
                int x = tid * 4 + it;               // 0..1023
                int r = x >> 3, c8 = x & 7;
                cpa16(base + r * 144 + c8 * 16,         hHi + (size_t)(m0 + r) * HID + kc * 64 + c8 * 8);
                cpa16(base + 18432 + r * 144 + c8 * 16, hLo + (size_t)(m0 + r) * HID + kc * 64 + c8 * 8);
            }
        };

        ldA(0, 0); cp_commit();
        for (int kc = 0; kc < 8; ++kc) {
            if (kc < 7) { ldA(kc + 1, (kc + 1) & 1); cp_commit(); cp_wait1(); }
            else cp_wait0();
            __syncthreads();
            char* base = smem + PS_A + (kc & 1) * PS_ABUF;
            const bf16* Ahi = (const bf16*)base;
            const bf16* Alo = (const bf16*)(base + 18432);
            #pragma unroll
            for (int ks = 0; ks < 4; ++ks) {
                wmma::fragment<wmma::matrix_a, 16, 16, 16, bf16, wmma::row_major> ahi[2], alo[2];
                wmma::fragment<wmma::matrix_b, 16, 16, 16, bf16, wmma::row_major> bhi[2], blo[2];
                #pragma unroll
                for (int i = 0; i < 2; i++) {
                    wmma::load_matrix_sync(ahi[i], Ahi + (wr * 32 + i * 16) * 72 + ks * 16, 72);
                    wmma::load_matrix_sync(alo[i], Alo + (wr * 32 + i * 16) * 72 + ks * 16, 72);
                }
                #pragma unroll
                for (int j = 0; j < 2; j++) {
                    wmma::load_matrix_sync(bhi[j], sWhi + (kc * 64 + ks * 16) * 64 + wc * 32 + j * 16, 64);
                    wmma::load_matrix_sync(blo[j], sWlo + (kc * 64 + ks * 16) * 64 + wc * 32 + j * 16, 64);
                }
                #pragma unroll
                for (int i = 0; i < 2; i++)
                    #pragma unroll
                    for (int j = 0; j < 2; j++) {
                        wmma::mma_sync(acc[i][j], ahi[i], bhi[j], acc[i][j]);
                        wmma::mma_sync(acc[i][j], ahi[i], blo[j], acc[i][j]);
                        wmma::mma_sync(acc[i][j], alo[i], bhi[j], acc[i][j]);
                    }
            }
            // q_in partial: h[qr][k] * WqH[k][q], k in this chunk's half
            {
                const float* wq = sWqH + (kc * 64 + qh * 32) * 8;
                const bf16* ah = Ahi + qr * 72 + qh * 32;
                const bf16* al = Alo + qr * 72 + qh * 32;
                #pragma unroll 8
                for (int kk = 0; kk < 32; ++kk) {
                    float hv = __bfloat162float(ah[kk]) + __bfloat162float(al[kk]);
                    #pragma unroll
                    for (int q = 0; q < NQV; q++) qacc[q] += hv * wq[kk * 8 + q];
                }
            }
            __syncthreads();
        }

        // --- epilogue ---
        float* sP = (float*)(smem + PS_A);
        float* sZ = (float*)(smem + PS_A + 32768);
        float* sQ = (float*)(smem + PS_A + 49152);
        #pragma unroll
        for (int i = 0; i < 2; i++)
            #pragma unroll
            for (int j = 0; j < 2; j++)
                wmma::store_matrix_sync(sP + (wr * 32 + i * 16) * 64 + wc * 32 + j * 16,
                                        acc[i][j], 64, wmma::mem_row_major);
        #pragma unroll
        for (int q = 0; q < NQV; q++) sQ[(qr * 2 + qh) * 8 + q] = qacc[q];
        __syncthreads();

        if (tid < 128) {
            const float* xq = g_XQ + ((size_t)t * BATCH + m0 + tid) * NQV;
            float qin[NQV];
            #pragma unroll
            for (int q = 0; q < NQV; q++)
                qin[q] = sQ[(tid * 2) * 8 + q] + sQ[(tid * 2 + 1) * 8 + q] + xq[q];
            float* z = sZ + tid * 32;
            #pragma unroll
            for (int g = 0; g < 4; ++g) {
                float run = 1.f;
                #pragma unroll
                for (int q = 0; q < NQV; ++q) {
                    run *= cosf(qin[q] + sTh[g * 8 + q]);
                    z[g * 8 + q] = run;
                }
            }
        }
        __syncthreads();

        {
            const int r = tid >> 1;
            const int jb = (tid & 1) * 8;
            const int rowg = m0 + r;
            const float* z = sZ + r * 32;
            const float* xp = g_XP + ((size_t)t * BATCH + rowg) * NTOT + nc0;
            const float* sPr = sP + r * 64;
            const size_t ob = ((size_t)t * BATCH + rowg) * HID;
            bf16* whi = g_hHi[wbuf] + (size_t)rowg * HID;
            bf16* wlo = g_hLo[wbuf] + (size_t)rowg * HID;
            #pragma unroll
            for (int jj = 0; jj < 8; ++jj) {
                int jl = jb + jj;
                int jg = nt * 16 + jl;
                float p0 = sPr[jl * 4 + 0] + xp[jl * 4 + 0] + sBias[jl * 4 + 0];
                float p1 = sPr[jl * 4 + 1] + xp[jl * 4 + 1] + sBias[jl * 4 + 1];
                float p2 = sPr[jl * 4 + 2] + xp[jl * 4 + 2] + sBias[jl * 4 + 2];
                float p3 = sPr[jl * 4 + 3] + xp[jl * 4 + 3] + sBias[jl * 4 + 3];
                float a0 = sBqh[jl], a1 = a0, a2 = a0, a3 = a0;
                #pragma unroll
                for (int q = 0; q < NQV; q++) {
                    float w = sWqhS[q * 16 + jl];
                    a0 += z[0 * 8 + q] * w;
                    a1 += z[1 * 8 + q] * w;
                    a2 += z[2 * 8 + q] * w;
                    a3 += z[3 * 8 + q] * w;
                }
                float f  = ALPHA_F * sigm(p0)  + ALPHB_F * sigm(a0);
                float ii = ALPHA_F * sigm(p1)  + ALPHB_F * sigm(a1);
                float gg = ALPHA_F * tanhf(p2) + ALPHB_F * tanhf(a2);
                float oo = ALPHA_F * sigm(p3)  + ALPHB_F * sigm(a3);
                float cn = f * c_state[jj] + ii * gg;
                float hn = oo * tanhf(cn);
                c_state[jj] = cn;
                out[ob + jg] = hn;
                bf16 hh = __float2bfloat16_rn(hn);
                whi[jg] = hh;
                wlo[jg] = __float2bfloat16_rn(hn - __bfloat162float(hh));
                if (t == T_STEPS - 1 && tails) {
                    size_t outT = (size_t)T_STEPS * BATCH * HID;
                    out[outT + (size_t)rowg * HID + jg] = hn;
                    out[outT + (size_t)BATCH * HID + (size_t)rowg * HID + jg] = cn;
                }
            }
        }
        grid_barrier();
    }
}

// ---------------- launch ------------------------------------------------------
extern "C" void kernel_launch(void* const* d_in, const int* in_sizes, int n_in,
                              void* d_out, int out_size)
{
    const float* inputs = (const float*)d_in[0];
    const float* Wf = (const float*)d_in[1];
    const float* bf_ = (const float*)d_in[2];
    const float* Wi = (const float*)d_in[3];
    const float* bi = (const float*)d_in[4];
    const float* Wu = (const float*)d_in[5];
    const float* bu = (const float*)d_in[6];
    const float* Wo = (const float*)d_in[7];
    const float* bo = (const float*)d_in[8];
    const float* Wq = (const float*)d_in[9];
    const float* bq = (const float*)d_in[10];
    const float* Wqh = (const float*)d_in[11];
    const float* bqh = (const float*)d_in[12];
    const float* th_f = (const float*)d_in[13];
    const float* th_i = (const float*)d_in[14];
    const float* th_u = (const float*)d_in[15];
    const float* th_o = (const float*)d_in[16];
    float* out = (float*)d_out;

    static int attr_done = 0;
    if (!attr_done) {
        cudaFuncSetAttribute(gemm_x, cudaFuncAttributeMaxDynamicSharedMemorySize, 2 * GX_BUF);
        cudaFuncSetAttribute(qlstm_persistent, cudaFuncAttributeMaxDynamicSharedMemorySize, PS_TOTAL);
        attr_done = 1;
    }

    const size_t outT = (size_t)T_STEPS * BATCH * HID;
    int tails = ((size_t)out_size >= outT + 2 * (size_t)BATCH * HID) ? 1 : 0;

    zero_state<<<(2 * BATCH * HID + 255) / 256, 256>>>();
    cvt_x<<<(int)(((size_t)MROWS * DIM + 255) / 256), 256>>>(inputs);
    cvt_w<<<(512 * NTOT + 255) / 256, 256>>>(Wf, Wi, Wu, Wo, bf_, bi, bu, bo);
    xq_kernel<<<MROWS / 16, 512>>>(inputs, Wq, bq);
    gemm_x<<<dim3(NTOT / 128, MROWS / 128), 256, 2 * GX_BUF>>>();
    qlstm_persistent<<<NBLOCKS, 256, PS_TOTAL>>>(
        Wq, Wqh, bqh, th_f, th_i, th_u, th_o, out, tails);
}

// round 4
// speedup vs baseline: 2.4184x; 1.5398x over previous
#include <cuda_runtime.h>
#include <cuda_bf16.h>
#include <mma.h>
#include <cstdint>

using namespace nvcuda;
typedef __nv_bfloat16 bf16;

#define T_STEPS 256
#define BATCH   512
#define DIM     512
#define HID     512
#define NQV     8
#define NTOT    2048
#define MROWS   (T_STEPS*BATCH)
#define ALPHA_F 0.7f
#define ALPHB_F 0.3f
#define NBLOCKS 128

// ---------------- device-global scratch (no allocations allowed) ------------
__device__ float g_XP[(size_t)MROWS * NTOT];      // x-part preacts (interleaved cols)
__device__ float g_XQ[(size_t)MROWS * NQV];       // x-part of q_in + bq
__device__ bf16  g_Xhi[(size_t)MROWS * DIM];
__device__ bf16  g_Xlo[(size_t)MROWS * DIM];
__device__ bf16  g_WxHi[512 * NTOT];              // interleaved: [k][4j+g] = Wg[k][j]
__device__ bf16  g_WxLo[512 * NTOT];
__device__ bf16  g_WhHi[512 * NTOT];              // [k][4j+g] = Wg[512+k][j]
__device__ bf16  g_WhLo[512 * NTOT];
__device__ float g_biasI[NTOT];                   // [4j+g] = b_g[j]
__device__ bf16  g_hHi[2][BATCH * HID];           // double-buffered h (split)
__device__ bf16  g_hLo[2][BATCH * HID];
__device__ unsigned g_arrive;
__device__ volatile unsigned g_gen;

__device__ __forceinline__ float sigm(float x) { return 1.f / (1.f + expf(-x)); }

__device__ __forceinline__ void cpa16(void* s, const void* g) {
    unsigned sa = (unsigned)__cvta_generic_to_shared(s);
    asm volatile("cp.async.cg.shared.global [%0], [%1], 16;\n" :: "r"(sa), "l"(g));
}
__device__ __forceinline__ void cp_commit() { asm volatile("cp.async.commit_group;\n" ::: "memory"); }
__device__ __forceinline__ void cp_wait1()  { asm volatile("cp.async.wait_group 1;\n" ::: "memory"); }
__device__ __forceinline__ void cp_wait0()  { asm volatile("cp.async.wait_group 0;\n" ::: "memory"); }

// ---------------- init: zero h buffers + barrier state -----------------------
__global__ void zero_state() {
    int i = blockIdx.x * blockDim.x + threadIdx.x;
    if (i < 2 * BATCH * HID) {
        ((bf16*)g_hHi)[i] = __float2bfloat16(0.f);
        ((bf16*)g_hLo)[i] = __float2bfloat16(0.f);
    }
    if (i == 0) { g_arrive = 0; g_gen = 0; }
}

// ---------------- split inputs into bf16 hi/lo --------------------------------
__global__ void cvt_x(const float* __restrict__ x) {
    size_t i = (size_t)blockIdx.x * blockDim.x + threadIdx.x;
    if (i >= (size_t)MROWS * DIM) return;
    float v = x[i];
    bf16 h = __float2bfloat16_rn(v);
    g_Xhi[i] = h;
    g_Xlo[i] = __float2bfloat16_rn(v - __bfloat162float(h));
}

// ---------------- build interleaved split weights + bias ----------------------
__global__ void cvt_w(const float* __restrict__ w0, const float* __restrict__ w1,
                      const float* __restrict__ w2, const float* __restrict__ w3,
                      const float* __restrict__ b0, const float* __restrict__ b1,
                      const float* __restrict__ b2, const float* __restrict__ b3) {
    int i = blockIdx.x * blockDim.x + threadIdx.x;
    if (i >= 512 * NTOT) return;
    int k = i >> 11, np = i & (NTOT - 1);
    int j = np >> 2, g = np & 3;
    const float* W = (g == 0) ? w0 : (g == 1) ? w1 : (g == 2) ? w2 : w3;
    float vx = W[(size_t)k * 512 + j];
    float vh = W[(size_t)(512 + k) * 512 + j];
    bf16 hx = __float2bfloat16_rn(vx);
    g_WxHi[i] = hx;
    g_WxLo[i] = __float2bfloat16_rn(vx - __bfloat162float(hx));
    bf16 hh = __float2bfloat16_rn(vh);
    g_WhHi[i] = hh;
    g_WhLo[i] = __float2bfloat16_rn(vh - __bfloat162float(hh));
    if (k == 0) {
        const float* B = (g == 0) ? b0 : (g == 1) ? b1 : (g == 2) ? b2 : b3;
        g_biasI[np] = B[j];
    }
}

// ---------------- XQ = inputs @ Wq[0:512] + bq -------------------------------
// 512 threads = 16 warps; one warp per row; Wq cached in smem transposed+padded
__global__ void __launch_bounds__(512) xq_kernel(
    const float* __restrict__ inputs, const float* __restrict__ Wq,
    const float* __restrict__ bq)
{
    __shared__ float sWq[NQV * 513];     // [q][k], pad 513 -> conflict-free
    __shared__ float sBq[NQV];
    int tid = threadIdx.x;
    for (int i = tid; i < 512 * NQV; i += 512) {
        int k = i >> 3, q = i & 7;
        sWq[q * 513 + k] = Wq[(size_t)k * NQV + q];
    }
    if (tid < NQV) sBq[tid] = bq[tid];
    __syncthreads();

    int gw   = blockIdx.x * 16 + (tid >> 5);
    int lane = tid & 31;
    const float* x = inputs + (size_t)gw * DIM;
    float acc[NQV];
    #pragma unroll
    for (int q = 0; q < NQV; q++) acc[q] = 0.f;
    #pragma unroll 4
    for (int k = lane; k < DIM; k += 32) {
        float xv = x[k];
        #pragma unroll
        for (int q = 0; q < NQV; q++) acc[q] += xv * sWq[q * 513 + k];
    }
    #pragma unroll
    for (int q = 0; q < NQV; q++) {
        float v = acc[q];
        #pragma unroll
        for (int off = 16; off; off >>= 1) v += __shfl_xor_sync(0xffffffffu, v, off);
        acc[q] = v;
    }
    if (lane == 0) {
        #pragma unroll
        for (int q = 0; q < NQV; q++) g_XQ[(size_t)gw * NQV + q] = acc[q] + sBq[q];
    }
}

// ---------------- precompute GEMM: XP = Xsplit @ Wx' (bf16x3, no bias) --------
// grid (16 Ntiles, 1024 Mtiles), 256 threads, cp.async 2-stage, padded smem
#define GA_LD 40
#define GB_LD 136
#define GX_AHI 0
#define GX_ALO 10240
#define GX_BHI 20480
#define GX_BLO 29184
#define GX_BUF 37888
__global__ void __launch_bounds__(256, 2) gemm_x()
{
    extern __shared__ char smem[];
    const int tid = threadIdx.x;
    const int n0 = blockIdx.x * 128;
    const size_t m0 = (size_t)blockIdx.y * 128;

    const int warp = tid >> 5;
    const int wr = warp & 3;      // M: 4 warps x 32 rows
    const int wc = warp >> 2;     // N: 2 warps x 64 cols

    wmma::fragment<wmma::accumulator, 16, 16, 16, float> acc[2][4];
    #pragma unroll
    for (int i = 0; i < 2; i++)
        #pragma unroll
        for (int j = 0; j < 4; j++) wmma::fill_fragment(acc[i][j], 0.f);

    auto ld_chunk = [&](int kc, int buf) {
        char* base = smem + buf * GX_BUF;
        #pragma unroll
        for (int it = 0; it < 2; ++it) {            // A: 128x32 hi+lo
            int x = tid * 2 + it;                   // 0..511
            int r = x >> 2, c4 = x & 3;
            cpa16(base + GX_AHI + r * 80 + c4 * 16, g_Xhi + (m0 + r) * DIM + kc * 32 + c4 * 8);
            cpa16(base + GX_ALO + r * 80 + c4 * 16, g_Xlo + (m0 + r) * DIM + kc * 32 + c4 * 8);
        }
        #pragma unroll
        for (int it = 0; it < 2; ++it) {            // B: 32x128 hi+lo
            int x = tid * 2 + it;
            int r = x >> 4, c16 = x & 15;
            cpa16(base + GX_BHI + r * 272 + c16 * 16, g_WxHi + (size_t)(kc * 32 + r) * NTOT + n0 + c16 * 8);
            cpa16(base + GX_BLO + r * 272 + c16 * 16, g_WxLo + (size_t)(kc * 32 + r) * NTOT + n0 + c16 * 8);
        }
    };

    ld_chunk(0, 0); cp_commit();
    for (int kc = 0; kc < 16; ++kc) {
        if (kc < 15) { ld_chunk(kc + 1, (kc + 1) & 1); cp_commit(); cp_wait1(); }
        else cp_wait0();
        __syncthreads();
        char* base = smem + (kc & 1) * GX_BUF;
        const bf16* Ahi = (const bf16*)(base + GX_AHI);
        const bf16* Alo = (const bf16*)(base + GX_ALO);
        const bf16* Bhi = (const bf16*)(base + GX_BHI);
        const bf16* Blo = (const bf16*)(base + GX_BLO);
        #pragma unroll
        for (int ks = 0; ks < 2; ++ks) {
            wmma::fragment<wmma::matrix_a, 16, 16, 16, bf16, wmma::row_major> ahi[2], alo[2];
            wmma::fragment<wmma::matrix_b, 16, 16, 16, bf16, wmma::row_major> bhi[4], blo[4];
            #pragma unroll
            for (int i = 0; i < 2; i++) {
                wmma::load_matrix_sync(ahi[i], Ahi + (wr * 32 + i * 16) * GA_LD + ks * 16, GA_LD);
                wmma::load_matrix_sync(alo[i], Alo + (wr * 32 + i * 16) * GA_LD + ks * 16, GA_LD);
            }
            #pragma unroll
            for (int j = 0; j < 4; j++) {
                wmma::load_matrix_sync(bhi[j], Bhi + (ks * 16) * GB_LD + wc * 64 + j * 16, GB_LD);
                wmma::load_matrix_sync(blo[j], Blo + (ks * 16) * GB_LD + wc * 64 + j * 16, GB_LD);
            }
            #pragma unroll
            for (int i = 0; i < 2; i++)
                #pragma unroll
                for (int j = 0; j < 4; j++) {
                    wmma::mma_sync(acc[i][j], ahi[i], bhi[j], acc[i][j]);
                    wmma::mma_sync(acc[i][j], ahi[i], blo[j], acc[i][j]);
                    wmma::mma_sync(acc[i][j], alo[i], bhi[j], acc[i][j]);
                }
        }
        __syncthreads();
    }
    #pragma unroll
    for (int i = 0; i < 2; i++)
        #pragma unroll
        for (int j = 0; j < 4; j++) {
            size_t row0 = m0 + wr * 32 + i * 16;
            int    col0 = n0 + wc * 64 + j * 16;
            wmma::store_matrix_sync(g_XP + row0 * NTOT + col0, acc[i][j], NTOT, wmma::mem_row_major);
        }
}

// ---------------- persistent recurrent kernel --------------------------------
// 512 threads, 16 warps: wr = warp&3 (32 rows), wc = warp>>2 (16 cols)
#define PS_W_HI  0        // 512x64 bf16 = 65536
#define PS_W_LO  65536
#define PS_A     131072   // 2 bufs x (hi 128x72 + lo 128x72) bf16 = 2*36864
#define PS_ABUF  36864
#define PS_ALD   72
#define PS_WQH   204800   // 512x8 f32 = 16384
#define PS_BIAS  221184   // 64 f32
#define PS_WQHS  221440   // 8x16 f32
#define PS_BQH   221952   // 16 f32
#define PS_TH    222016   // 32 f32
#define PS_TOTAL 222144
// epilogue alias over PS_A: sP 128x64 f32 (32KB), sZ 128x32 f32 @+32768, sQ 512x8 f32 @+49152

__device__ __forceinline__ void grid_barrier() {
    __syncthreads();
    if (threadIdx.x == 0) {
        __threadfence();
        unsigned gen = g_gen;
        if (atomicAdd(&g_arrive, 1u) == NBLOCKS - 1) {
            g_arrive = 0;
            __threadfence();
            g_gen = gen + 1;
        } else {
            while (g_gen == gen) { }
            __threadfence();
        }
    }
    __syncthreads();
}

__global__ void __launch_bounds__(512, 1) qlstm_persistent(
    const float* __restrict__ Wq,  const float* __restrict__ Wqh,
    const float* __restrict__ bqh,
    const float* __restrict__ thf, const float* __restrict__ thi,
    const float* __restrict__ thu, const float* __restrict__ tho,
    float* __restrict__ out, int tails)
{
    extern __shared__ char smem[];
    const int tid = threadIdx.x;
    const int bx = blockIdx.x;           // 0..127
    const int mt = bx >> 5, nt = bx & 31;
    const int m0 = mt * 128;             // batch-row base
    const int nc0 = nt * 64;             // interleaved col base
    const int warp = tid >> 5;
    const int wr = warp & 3, wc = warp >> 2;   // wc 0..3 (16 cols each)

    bf16* sWhi = (bf16*)(smem + PS_W_HI);
    bf16* sWlo = (bf16*)(smem + PS_W_LO);
    for (int i = tid; i < 512 * 64; i += 512) {
        int k = i >> 6, nl = i & 63;
        sWhi[i] = g_WhHi[(size_t)k * NTOT + nc0 + nl];
        sWlo[i] = g_WhLo[(size_t)k * NTOT + nc0 + nl];
    }
    float* sWqH = (float*)(smem + PS_WQH);     // [k][q] fp32
    for (int i = tid; i < 512 * 8; i += 512)
        sWqH[i] = Wq[(size_t)(512 + (i >> 3)) * NQV + (i & 7)];
    float* sBias = (float*)(smem + PS_BIAS);
    if (tid < 64) sBias[tid] = g_biasI[nc0 + tid];
    float* sWqhS = (float*)(smem + PS_WQHS);
    if (tid < 128) sWqhS[tid] = Wqh[(size_t)(tid >> 4) * HID + nt * 16 + (tid & 15)];
    float* sBqh = (float*)(smem + PS_BQH);
    if (tid < 16) sBqh[tid] = bqh[nt * 16 + tid];
    float* sTh = (float*)(smem + PS_TH);
    if (tid < 32) {
        int g = tid >> 3, q = tid & 7;
        sTh[tid] = (g == 0) ? thf[q] : (g == 1) ? thi[q] : (g == 2) ? thu[q] : tho[q];
    }
    float c_state[4];
    #pragma unroll
    for (int i = 0; i < 4; i++) c_state[i] = 0.f;
    __syncthreads();

    const int qr = tid >> 2;             // row for q-accum (4 threads/row)
    const int qp = tid & 3;              // k-quarter (16 k) within 64-chunk

    for (int t = 0; t < T_STEPS; ++t) {
        const int rbuf = t & 1, wbuf = rbuf ^ 1;
        const bf16* hHi = g_hHi[rbuf];
        const bf16* hLo = g_hLo[rbuf];

        wmma::fragment<wmma::accumulator, 16, 16, 16, float> acch[2], accx[2];
        #pragma unroll
        for (int i = 0; i < 2; i++) { wmma::fill_fragment(acch[i], 0.f); wmma::fill_fragment(accx[i], 0.f); }

        float qacc[NQV];
        #pragma unroll
        for (int q = 0; q < NQV; q++) qacc[q] = 0.f;

        auto ldA = [&](int kc, int buf) {
            char* base = smem + PS_A + buf * PS_ABUF;
            #pragma unroll
            for (int it = 0; it < 2; ++it) {
                int x = tid * 2 + it;               // 0..1023
                int r = x >> 3, c8 = x & 7;
                cpa16(base + r * 144 + c8 * 16,         hHi + (size_t)(m0 + r) * HID + kc * 64 + c8 * 8);
                cpa16(base + 18432 + r * 144 + c8 * 16, hLo + (size_t)(m0 + r) * HID + kc * 64 + c8 * 8);
            }
        };

        ldA(0, 0); cp_commit();
        for (int kc = 0; kc < 8; ++kc) {
            if (kc < 7) { ldA(kc + 1, (kc + 1) & 1); cp_commit(); cp_wait1(); }
            else cp_wait0();
            __syncthreads();
            char* base = smem + PS_A + (kc & 1) * PS_ABUF;
            const bf16* Ahi = (const bf16*)base;
            const bf16* Alo = (const bf16*)(base + 18432);
            #pragma unroll
            for (int ks = 0; ks < 4; ++ks) {
                wmma::fragment<wmma::matrix_a, 16, 16, 16, bf16, wmma::row_major> ahi[2], alo[2];
                wmma::fragment<wmma::matrix_b, 16, 16, 16, bf16, wmma::row_major> bhi, blo;
                #pragma unroll
                for (int i = 0; i < 2; i++) {
                    wmma::load_matrix_sync(ahi[i], Ahi + (wr * 32 + i * 16) * PS_ALD + ks * 16, PS_ALD);
                    wmma::load_matrix_sync(alo[i], Alo + (wr * 32 + i * 16) * PS_ALD + ks * 16, PS_ALD);
                }
                wmma::load_matrix_sync(bhi, sWhi + (kc * 64 + ks * 16) * 64 + wc * 16, 64);
                wmma::load_matrix_sync(blo, sWlo + (kc * 64 + ks * 16) * 64 + wc * 16, 64);
                #pragma unroll
                for (int i = 0; i < 2; i++) {
                    wmma::mma_sync(acch[i], ahi[i], bhi, acch[i]);  // chain A
                    wmma::mma_sync(accx[i], ahi[i], blo, accx[i]);  // chain B
                    wmma::mma_sync(accx[i], alo[i], bhi, accx[i]);
                }
            }
            // q_in partial: h[qr][k] * WqH[k][q]
            {
                const float* wq = sWqH + (kc * 64 + qp * 16) * 8;
                const bf16* ah = Ahi + qr * PS_ALD + qp * 16;
                const bf16* al = Alo + qr * PS_ALD + qp * 16;
                #pragma unroll
                for (int kk = 0; kk < 16; ++kk) {
                    float hv = __bfloat162float(ah[kk]) + __bfloat162float(al[kk]);
                    #pragma unroll
                    for (int q = 0; q < NQV; q++) qacc[q] += hv * wq[kk * 8 + q];
                }
            }
            __syncthreads();
        }

        // --- epilogue ---
        float* sP = (float*)(smem + PS_A);
        float* sZ = (float*)(smem + PS_A + 32768);
        float* sQ = (float*)(smem + PS_A + 49152);
        #pragma unroll
        for (int i = 0; i < 2; i++) {
            #pragma unroll
            for (int e = 0; e < acch[i].num_elements; ++e) acch[i].x[e] += accx[i].x[e];
            wmma::store_matrix_sync(sP + (wr * 32 + i * 16) * 64 + wc * 16, acch[i], 64, wmma::mem_row_major);
        }
        #pragma unroll
        for (int q = 0; q < NQV; q++) sQ[tid * 8 + q] = qacc[q];
        __syncthreads();

        // qin + cumprod(cos): thread = (row, gate)
        {
            const int r = tid >> 2, g = tid & 3;
            const float* xq = g_XQ + ((size_t)t * BATCH + m0 + r) * NQV;
            float qin[NQV];
            #pragma unroll
            for (int q = 0; q < NQV; q++)
                qin[q] = sQ[(r * 4 + 0) * 8 + q] + sQ[(r * 4 + 1) * 8 + q]
                       + sQ[(r * 4 + 2) * 8 + q] + sQ[(r * 4 + 3) * 8 + q] + xq[q];
            float run = 1.f;
            #pragma unroll
            for (int q = 0; q < NQV; ++q) {
                run *= cosf(qin[q] + sTh[g * 8 + q]);
                sZ[r * 32 + g * 8 + q] = run;
            }
        }
        __syncthreads();

        // gate combine + LSTM update: thread = (row, col-quad)
        {
            const int r = tid >> 2;
            const int qd = tid & 3;            // 16 interleaved cols = 4 h-cols
            const int rowg = m0 + r;
            const float* z = sZ + r * 32;
            const float4* xp4 = (const float4*)(g_XP + ((size_t)t * BATCH + rowg) * NTOT + nc0 + qd * 16);
            const float* sPr = sP + r * 64 + qd * 16;
            const float* sBq_ = sBias + qd * 16;
            const size_t ob = ((size_t)t * BATCH + rowg) * HID;
            bf16* whi = g_hHi[wbuf] + (size_t)rowg * HID;
            bf16* wlo = g_hLo[wbuf] + (size_t)rowg * HID;
            #pragma unroll
            for (int jj = 0; jj < 4; ++jj) {
                int jl = qd * 4 + jj;
                int jg = nt * 16 + jl;
                float4 xv = xp4[jj];
                float p0 = sPr[jj * 4 + 0] + xv.x + sBq_[jj * 4 + 0];
                float p1 = sPr[jj * 4 + 1] + xv.y + sBq_[jj * 4 + 1];
                float p2 = sPr[jj * 4 + 2] + xv.z + sBq_[jj * 4 + 2];
                float p3 = sPr[jj * 4 + 3] + xv.w + sBq_[jj * 4 + 3];
                float a0 = sBqh[jl], a1 = a0, a2 = a0, a3 = a0;
                #pragma unroll
                for (int q = 0; q < NQV; q++) {
                    float w = sWqhS[q * 16 + jl];
                    a0 += z[0 * 8 + q] * w;
                    a1 += z[1 * 8 + q] * w;
                    a2 += z[2 * 8 + q] * w;
                    a3 += z[3 * 8 + q] * w;
                }
                float f  = ALPHA_F * sigm(p0)  + ALPHB_F * sigm(a0);
                float ii = ALPHA_F * sigm(p1)  + ALPHB_F * sigm(a1);
                float gg = ALPHA_F * tanhf(p2) + ALPHB_F * tanhf(a2);
                float oo = ALPHA_F * sigm(p3)  + ALPHB_F * sigm(a3);
                float cn = f * c_state[jj] + ii * gg;
                float hn = oo * tanhf(cn);
                c_state[jj] = cn;
                out[ob + jg] = hn;
                bf16 hh = __float2bfloat16_rn(hn);
                whi[jg] = hh;
                wlo[jg] = __float2bfloat16_rn(hn - __bfloat162float(hh));
                if (t == T_STEPS - 1 && tails) {
                    size_t outT = (size_t)T_STEPS * BATCH * HID;
                    out[outT + (size_t)rowg * HID + jg] = hn;
                    out[outT + (size_t)BATCH * HID + (size_t)rowg * HID + jg] = cn;
                }
            }
        }
        grid_barrier();
    }
}

// ---------------- launch ------------------------------------------------------
extern "C" void kernel_launch(void* const* d_in, const int* in_sizes, int n_in,
                              void* d_out, int out_size)
{
    const float* inputs = (const float*)d_in[0];
    const float* Wf = (const float*)d_in[1];
    const float* bf_ = (const float*)d_in[2];
    const float* Wi = (const float*)d_in[3];
    const float* bi = (const float*)d_in[4];
    const float* Wu = (const float*)d_in[5];
    const float* bu = (const float*)d_in[6];
    const float* Wo = (const float*)d_in[7];
    const float* bo = (const float*)d_in[8];
    const float* Wq = (const float*)d_in[9];
    const float* bq = (const float*)d_in[10];
    const float* Wqh = (const float*)d_in[11];
    const float* bqh = (const float*)d_in[12];
    const float* th_f = (const float*)d_in[13];
    const float* th_i = (const float*)d_in[14];
    const float* th_u = (const float*)d_in[15];
    const float* th_o = (const float*)d_in[16];
    float* out = (float*)d_out;

    cudaFuncSetAttribute(gemm_x, cudaFuncAttributeMaxDynamicSharedMemorySize, 2 * GX_BUF);
    cudaFuncSetAttribute(qlstm_persistent, cudaFuncAttributeMaxDynamicSharedMemorySize, PS_TOTAL);

    const size_t outT = (size_t)T_STEPS * BATCH * HID;
    int tails = ((size_t)out_size >= outT + 2 * (size_t)BATCH * HID) ? 1 : 0;

    zero_state<<<(2 * BATCH * HID + 255) / 256, 256>>>();
    cvt_x<<<(int)(((size_t)MROWS * DIM + 255) / 256), 256>>>(inputs);
    cvt_w<<<(512 * NTOT + 255) / 256, 256>>>(Wf, Wi, Wu, Wo, bf_, bi, bu, bo);
    xq_kernel<<<MROWS / 16, 512>>>(inputs, Wq, bq);
    gemm_x<<<dim3(NTOT / 128, MROWS / 128), 256, 2 * GX_BUF>>>();
    qlstm_persistent<<<NBLOCKS, 512, PS_TOTAL>>>(
        Wq, Wqh, bqh, th_f, th_i, th_u, th_o, out, tails);
}

// round 9
// speedup vs baseline: 3.3534x; 1.3866x over previous
#include <cuda_runtime.h>
#include <cuda_bf16.h>
#include <mma.h>
#include <cstdint>

using namespace nvcuda;
typedef __nv_bfloat16 bf16;

#define T_STEPS 256
#define BATCH   512
#define DIM     512
#define HID     512
#define NQV     8
#define NTOT    2048
#define MROWS   (T_STEPS*BATCH)
#define ALPHA_F 0.7f
#define ALPHB_F 0.3f
#define NBLOCKS 128

// ---------------- device-global scratch (no allocations allowed) ------------
__device__ float g_XP[(size_t)MROWS * NTOT];      // x-part preacts (interleaved cols)
__device__ float g_XQ[(size_t)MROWS * NQV];       // x-part of q_in + bq
__device__ bf16  g_Xhi[(size_t)MROWS * DIM];
__device__ bf16  g_Xlo[(size_t)MROWS * DIM];
__device__ bf16  g_WxHi[512 * NTOT];              // interleaved: [k][4j+g] = Wg[k][j]
__device__ bf16  g_WxLo[512 * NTOT];
__device__ bf16  g_WhHi[512 * NTOT];              // [k][4j+g] = Wg[512+k][j]
__device__ bf16  g_WhLo[512 * NTOT];
__device__ float g_biasI[NTOT];                   // [4j+g] = b_g[j]
// h in row-blocked transposed layout: [buf][mt][col(512)][row(128)]
__device__ bf16  g_hThi[2 * 4 * 512 * 128];
__device__ bf16  g_hTlo[2 * 4 * 512 * 128];
__device__ unsigned g_arr[4];
__device__ volatile unsigned g_genA[4];

__device__ __forceinline__ float sigm(float x) { return 1.f / (1.f + expf(-x)); }

__device__ __forceinline__ void cpa16(void* s, const void* g) {
    unsigned sa = (unsigned)__cvta_generic_to_shared(s);
    asm volatile("cp.async.cg.shared.global [%0], [%1], 16;\n" :: "r"(sa), "l"(g));
}
__device__ __forceinline__ void cp_commit() { asm volatile("cp.async.commit_group;\n" ::: "memory"); }
__device__ __forceinline__ void cp_wait1()  { asm volatile("cp.async.wait_group 1;\n" ::: "memory"); }
__device__ __forceinline__ void cp_wait0()  { asm volatile("cp.async.wait_group 0;\n" ::: "memory"); }

// ---- bulk async copy + mbarrier helpers (sm_90+) ----
__device__ __forceinline__ void bulk_cp(unsigned dst_s, const void* src, unsigned bytes, unsigned mbar_s) {
    asm volatile("cp.async.bulk.shared::cta.global.mbarrier::complete_tx::bytes [%0], [%1], %2, [%3];"
                 :: "r"(dst_s), "l"(src), "r"(bytes), "r"(mbar_s) : "memory");
}
__device__ __forceinline__ void mbar_init(unsigned mbar_s, unsigned cnt) {
    asm volatile("mbarrier.init.shared.b64 [%0], %1;" :: "r"(mbar_s), "r"(cnt) : "memory");
}
__device__ __forceinline__ void mbar_expect(unsigned mbar_s, unsigned bytes) {
    asm volatile("mbarrier.arrive.expect_tx.shared.b64 _, [%0], %1;" :: "r"(mbar_s), "r"(bytes) : "memory");
}
__device__ __forceinline__ void mbar_wait(unsigned mbar_s, unsigned parity) {
    asm volatile(
        "{\n\t.reg .pred P;\n"
        "LW_%=:\n\t"
        "mbarrier.try_wait.parity.acquire.cta.shared::cta.b64 P, [%0], %1, 0x989680;\n\t"
        "@P bra LD_%=;\n\t"
        "bra LW_%=;\n"
        "LD_%=:\n\t}"
        :: "r"(mbar_s), "r"(parity) : "memory");
}

// ---------------- init: zero h buffers + barrier state -----------------------
__global__ void zero_state() {
    int i = blockIdx.x * blockDim.x + threadIdx.x;
    if (i < 2 * 4 * 512 * 128) {
        g_hThi[i] = __float2bfloat16(0.f);
        g_hTlo[i] = __float2bfloat16(0.f);
    }
    if (i < 4) { g_arr[i] = 0; g_genA[i] = 0; }
}

// ---------------- split inputs into bf16 hi/lo --------------------------------
__global__ void cvt_x(const float* __restrict__ x) {
    size_t i = (size_t)blockIdx.x * blockDim.x + threadIdx.x;
    if (i >= (size_t)MROWS * DIM) return;
    float v = x[i];
    bf16 h = __float2bfloat16_rn(v);
    g_Xhi[i] = h;
    g_Xlo[i] = __float2bfloat16_rn(v - __bfloat162float(h));
}

// ---------------- build interleaved split weights + bias ----------------------
__global__ void cvt_w(const float* __restrict__ w0, const float* __restrict__ w1,
                      const float* __restrict__ w2, const float* __restrict__ w3,
                      const float* __restrict__ b0, const float* __restrict__ b1,
                      const float* __restrict__ b2, const float* __restrict__ b3) {
    int i = blockIdx.x * blockDim.x + threadIdx.x;
    if (i >= 512 * NTOT) return;
    int k = i >> 11, np = i & (NTOT - 1);
    int j = np >> 2, g = np & 3;
    const float* W = (g == 0) ? w0 : (g == 1) ? w1 : (g == 2) ? w2 : w3;
    float vx = W[(size_t)k * 512 + j];
    float vh = W[(size_t)(512 + k) * 512 + j];
    bf16 hx = __float2bfloat16_rn(vx);
    g_WxHi[i] = hx;
    g_WxLo[i] = __float2bfloat16_rn(vx - __bfloat162float(hx));
    bf16 hh = __float2bfloat16_rn(vh);
    g_WhHi[i] = hh;
    g_WhLo[i] = __float2bfloat16_rn(vh - __bfloat162float(hh));
    if (k == 0) {
        const float* B = (g == 0) ? b0 : (g == 1) ? b1 : (g == 2) ? b2 : b3;
        g_biasI[np] = B[j];
    }
}

// ---------------- XQ = inputs @ Wq[0:512] + bq -------------------------------
__global__ void __launch_bounds__(512) xq_kernel(
    const float* __restrict__ inputs, const float* __restrict__ Wq,
    const float* __restrict__ bq)
{
    __shared__ float sWq[NQV * 513];
    __shared__ float sBq[NQV];
    int tid = threadIdx.x;
    for (int i = tid; i < 512 * NQV; i += 512) {
        int k = i >> 3, q = i & 7;
        sWq[q * 513 + k] = Wq[(size_t)k * NQV + q];
    }
    if (tid < NQV) sBq[tid] = bq[tid];
    __syncthreads();

    int gw   = blockIdx.x * 16 + (tid >> 5);
    int lane = tid & 31;
    const float* x = inputs + (size_t)gw * DIM;
    float acc[NQV];
    #pragma unroll
    for (int q = 0; q < NQV; q++) acc[q] = 0.f;
    #pragma unroll 4
    for (int k = lane; k < DIM; k += 32) {
        float xv = x[k];
        #pragma unroll
        for (int q = 0; q < NQV; q++) acc[q] += xv * sWq[q * 513 + k];
    }
    #pragma unroll
    for (int q = 0; q < NQV; q++) {
        float v = acc[q];
        #pragma unroll
        for (int off = 16; off; off >>= 1) v += __shfl_xor_sync(0xffffffffu, v, off);
        acc[q] = v;
    }
    if (lane == 0) {
        #pragma unroll
        for (int q = 0; q < NQV; q++) g_XQ[(size_t)gw * NQV + q] = acc[q] + sBq[q];
    }
}

// ---------------- precompute GEMM: XP = Xsplit @ Wx' (bf16x3, no bias) --------
#define GA_LD 40
#define GB_LD 136
#define GX_AHI 0
#define GX_ALO 10240
#define GX_BHI 20480
#define GX_BLO 29184
#define GX_BUF 37888
__global__ void __launch_bounds__(256, 2) gemm_x()
{
    extern __shared__ char smem[];
    const int tid = threadIdx.x;
    const int n0 = blockIdx.x * 128;
    const size_t m0 = (size_t)blockIdx.y * 128;

    const int warp = tid >> 5;
    const int wr = warp & 3;
    const int wc = warp >> 2;

    wmma::fragment<wmma::accumulator, 16, 16, 16, float> acc[2][4];
    #pragma unroll
    for (int i = 0; i < 2; i++)
        #pragma unroll
        for (int j = 0; j < 4; j++) wmma::fill_fragment(acc[i][j], 0.f);

    auto ld_chunk = [&](int kc, int buf) {
        char* base = smem + buf * GX_BUF;
        #pragma unroll
        for (int it = 0; it < 2; ++it) {
            int x = tid * 2 + it;
            int r = x >> 2, c4 = x & 3;
            cpa16(base + GX_AHI + r * 80 + c4 * 16, g_Xhi + (m0 + r) * DIM + kc * 32 + c4 * 8);
            cpa16(base + GX_ALO + r * 80 + c4 * 16, g_Xlo + (m0 + r) * DIM + kc * 32 + c4 * 8);
        }
        #pragma unroll
        for (int it = 0; it < 2; ++it) {
            int x = tid * 2 + it;
            int r = x >> 4, c16 = x & 15;
            cpa16(base + GX_BHI + r * 272 + c16 * 16, g_WxHi + (size_t)(kc * 32 + r) * NTOT + n0 + c16 * 8);
            cpa16(base + GX_BLO + r * 272 + c16 * 16, g_WxLo + (size_t)(kc * 32 + r) * NTOT + n0 + c16 * 8);
        }
    };

    ld_chunk(0, 0); cp_commit();
    for (int kc = 0; kc < 16; ++kc) {
        if (kc < 15) { ld_chunk(kc + 1, (kc + 1) & 1); cp_commit(); cp_wait1(); }
        else cp_wait0();
        __syncthreads();
        char* base = smem + (kc & 1) * GX_BUF;
        const bf16* Ahi = (const bf16*)(base + GX_AHI);
        const bf16* Alo = (const bf16*)(base + GX_ALO);
        const bf16* Bhi = (const bf16*)(base + GX_BHI);
        const bf16* Blo = (const bf16*)(base + GX_BLO);
        #pragma unroll
        for (int ks = 0; ks < 2; ++ks) {
            wmma::fragment<wmma::matrix_a, 16, 16, 16, bf16, wmma::row_major> ahi[2], alo[2];
            wmma::fragment<wmma::matrix_b, 16, 16, 16, bf16, wmma::row_major> bhi[4], blo[4];
            #pragma unroll
            for (int i = 0; i < 2; i++) {
                wmma::load_matrix_sync(ahi[i], Ahi + (wr * 32 + i * 16) * GA_LD + ks * 16, GA_LD);
                wmma::load_matrix_sync(alo[i], Alo + (wr * 32 + i * 16) * GA_LD + ks * 16, GA_LD);
            }
            #pragma unroll
            for (int j = 0; j < 4; j++) {
                wmma::load_matrix_sync(bhi[j], Bhi + (ks * 16) * GB_LD + wc * 64 + j * 16, GB_LD);
                wmma::load_matrix_sync(blo[j], Blo + (ks * 16) * GB_LD + wc * 64 + j * 16, GB_LD);
            }
            #pragma unroll
            for (int i = 0; i < 2; i++)
                #pragma unroll
                for (int j = 0; j < 4; j++) {
                    wmma::mma_sync(acc[i][j], ahi[i], bhi[j], acc[i][j]);
                    wmma::mma_sync(acc[i][j], ahi[i], blo[j], acc[i][j]);
                    wmma::mma_sync(acc[i][j], alo[i], bhi[j], acc[i][j]);
                }
        }
        __syncthreads();
    }
    #pragma unroll
    for (int i = 0; i < 2; i++)
        #pragma unroll
        for (int j = 0; j < 4; j++) {
            size_t row0 = m0 + wr * 32 + i * 16;
            int    col0 = n0 + wc * 64 + j * 16;
            wmma::store_matrix_sync(g_XP + row0 * NTOT + col0, acc[i][j], NTOT, wmma::mem_row_major);
        }
}

// ---------------- persistent recurrent kernel --------------------------------
// smem map (bytes):
#define SW_HI   0         // 512 x 72 bf16 = 73728
#define SW_LO   73728
#define SQW     147456    // 512 x 24 bf16 = 24576 (cols 0-7 WqH hi, 8-15 WqH lo)
#define ST_A    172032    // 2 stages x 17408 (hi 32x136 bf16, lo at +8704)
#define ST_ABUF 17408
#define SQM     206848    // 128 x 16 f32 = 8192
#define SBIAS   215040    // 64 f32
#define SWQHS   215296    // 8 x 16 f32
#define SBQH    215808    // 16 f32
#define STH     215872    // 32 f32
#define SMB     216000    // 2 mbarriers (16B)
#define PS_TOTAL 216064
// epilogue alias over ST_A: sP 128 x 68 f32 = 34816

#define W_LD  72
#define QW_LD 24
#define A_LD  136
#define SP_LD 68

__global__ void __launch_bounds__(512) qlstm_persistent(
    const float* __restrict__ Wq,  const float* __restrict__ Wqh,
    const float* __restrict__ bqh,
    const float* __restrict__ thf, const float* __restrict__ thi,
    const float* __restrict__ thu, const float* __restrict__ tho,
    float* __restrict__ out, int tails)
{
    extern __shared__ char smem[];
    const unsigned smem_u = (unsigned)__cvta_generic_to_shared(smem);
    const int tid = threadIdx.x;
    const int bx = blockIdx.x;
    const int mt = bx >> 5, nt = bx & 31;
    const int m0 = mt * 128;
    const int nc0 = nt * 64;
    const int warp = tid >> 5;
    const int wr = warp >> 1;            // 0..7 : 16 rows each
    const int wc = warp & 1;             // 0..1 : 32 cols each

    bf16* sWhi = (bf16*)(smem + SW_HI);
    bf16* sWlo = (bf16*)(smem + SW_LO);
    for (int i = tid; i < 512 * 64; i += 512) {
        int k = i >> 6, n = i & 63;
        sWhi[k * W_LD + n] = g_WhHi[(size_t)k * NTOT + nc0 + n];
        sWlo[k * W_LD + n] = g_WhLo[(size_t)k * NTOT + nc0 + n];
    }
    bf16* sQW = (bf16*)(smem + SQW);
    for (int i = tid; i < 512 * 16; i += 512) {
        int k = i >> 4, c = i & 15;
        float v = Wq[(size_t)(512 + k) * NQV + (c & 7)];
        bf16 h = __float2bfloat16_rn(v);
        sQW[k * QW_LD + c] = (c < 8) ? h : __float2bfloat16_rn(v - __bfloat162float(h));
    }
    float* sBias = (float*)(smem + SBIAS);
    if (tid < 64) sBias[tid] = g_biasI[nc0 + tid];
    float* sWqhS = (float*)(smem + SWQHS);
    if (tid < 128) sWqhS[tid] = Wqh[(size_t)(tid >> 4) * HID + nt * 16 + (tid & 15)];
    float* sBqh = (float*)(smem + SBQH);
    if (tid < 16) sBqh[tid] = bqh[nt * 16 + tid];
    float* sTh = (float*)(smem + STH);
    if (tid < 32) {
        int g = tid >> 3, q = tid & 7;
        sTh[tid] = (g == 0) ? thf[q] : (g == 1) ? thi[q] : (g == 2) ? thu[q] : tho[q];
    }
    const unsigned mb0 = smem_u + SMB, mb1 = smem_u + SMB + 8;
    if (tid == 0) { mbar_init(mb0, 1); mbar_init(mb1, 1); }
    float c_state[4];
    #pragma unroll
    for (int i = 0; i < 4; i++) c_state[i] = 0.f;
    __syncthreads();

    int ph0 = 0, ph1 = 0;

    for (int t = 0; t < T_STEPS; ++t) {
        const int rbuf = t & 1, wbuf = rbuf ^ 1;
        const bf16* hHiT = g_hThi + ((size_t)(rbuf * 4 + mt) * 512) * 128;
        const bf16* hLoT = g_hTlo + ((size_t)(rbuf * 4 + mt) * 512) * 128;

        wmma::fragment<wmma::accumulator, 16, 16, 16, float> acch[2], accx[2], accq;
        #pragma unroll
        for (int j = 0; j < 2; j++) { wmma::fill_fragment(acch[j], 0.f); wmma::fill_fragment(accx[j], 0.f); }
        wmma::fill_fragment(accq, 0.f);

        auto issue_chunk = [&](int kc, int stage) {
            if (tid < 32) {
                unsigned sbase = smem_u + ST_A + stage * ST_ABUF;
                if (tid == 0) mbar_expect(stage == 0 ? mb0 : mb1, 16384);
                unsigned mb = (stage == 0) ? mb0 : mb1;
                bulk_cp(sbase + tid * 272,        hHiT + (size_t)(kc * 32 + tid) * 128, 256, mb);
                bulk_cp(sbase + 8704 + tid * 272, hLoT + (size_t)(kc * 32 + tid) * 128, 256, mb);
            }
        };

        issue_chunk(0, 0);
        for (int kc = 0; kc < 16; ++kc) {
            int s = kc & 1;
            if (kc < 15) issue_chunk(kc + 1, s ^ 1);
            if (s == 0) { mbar_wait(mb0, ph0); ph0 ^= 1; }
            else        { mbar_wait(mb1, ph1); ph1 ^= 1; }

            const bf16* Ahi = (const bf16*)(smem + ST_A + s * ST_ABUF);
            const bf16* Alo = (const bf16*)(smem + ST_A + s * ST_ABUF + 8704);
            const int kb = kc * 32;
            #pragma unroll
            for (int ks = 0; ks < 2; ++ks) {
                wmma::fragment<wmma::matrix_a, 16, 16, 16, bf16, wmma::col_major> ahi, alo;
                wmma::load_matrix_sync(ahi, Ahi + (ks * 16) * A_LD + wr * 16, A_LD);
                wmma::load_matrix_sync(alo, Alo + (ks * 16) * A_LD + wr * 16, A_LD);
                #pragma unroll
                for (int j = 0; j < 2; j++) {
                    wmma::fragment<wmma::matrix_b, 16, 16, 16, bf16, wmma::row_major> bhi, blo;
                    wmma::load_matrix_sync(bhi, sWhi + (kb + ks * 16) * W_LD + wc * 32 + j * 16, W_LD);
                    wmma::load_matrix_sync(blo, sWlo + (kb + ks * 16) * W_LD + wc * 32 + j * 16, W_LD);
                    wmma::mma_sync(acch[j], ahi, bhi, acch[j]);
                    wmma::mma_sync(accx[j], ahi, blo, accx[j]);
                    wmma::mma_sync(accx[j], alo, bhi, accx[j]);
                }
                if (wc == 0) {
                    wmma::fragment<wmma::matrix_b, 16, 16, 16, bf16, wmma::row_major> bq;
                    wmma::load_matrix_sync(bq, sQW + (kb + ks * 16) * QW_LD, QW_LD);
                    wmma::mma_sync(accq, ahi, bq, accq);
                    wmma::mma_sync(accq, alo, bq, accq);
                }
            }
            __syncthreads();
        }

        // --- epilogue: store preacts + q into smem ---
        float* sP  = (float*)(smem + ST_A);
        float* sQm = (float*)(smem + SQM);
        #pragma unroll
        for (int j = 0; j < 2; j++) {
            #pragma unroll
            for (int e = 0; e < acch[j].num_elements; ++e) acch[j].x[e] += accx[j].x[e];
            wmma::store_matrix_sync(sP + (wr * 16) * SP_LD + wc * 32 + j * 16, acch[j], SP_LD, wmma::mem_row_major);
        }
        if (wc == 0)
            wmma::store_matrix_sync(sQm + (wr * 16) * 16, accq, 16, wmma::mem_row_major);
        __syncthreads();

        // phase1: thread = (row, gate): qin + cumprod(cos) -> z[8] in regs
        const int r = tid >> 2;
        const int gq = tid & 3;
        float z[NQV];
        {
            const float* xq = g_XQ + ((size_t)t * BATCH + m0 + r) * NQV;
            float run = 1.f;
            #pragma unroll
            for (int q = 0; q < NQV; ++q) {
                float qin = sQm[r * 16 + q] + sQm[r * 16 + 8 + q] + xq[q];
                run *= __cosf(qin + sTh[gq * 8 + q]);
                z[q] = run;
            }
        }
        // exchange z across the 4 lanes of this row (same warp)
        float zz[4][NQV];
        {
            const int lb = (tid & 31) & ~3;
            #pragma unroll
            for (int g = 0; g < 4; ++g)
                #pragma unroll
                for (int q = 0; q < NQV; ++q)
                    zz[g][q] = __shfl_sync(0xffffffffu, z[q], lb + g);
        }

        // phase2: thread = (row, col-quad): gate combine + LSTM update
        {
            const int qd = gq;
            const int rowg = m0 + r;
            const float4* xp4 = (const float4*)(g_XP + ((size_t)t * BATCH + rowg) * NTOT + nc0 + qd * 16);
            const float* sPr = sP + r * SP_LD + qd * 16;
            const float* sBq_ = sBias + qd * 16;
            const size_t ob = ((size_t)t * BATCH + rowg) * HID;
            bf16* whi = g_hThi + ((size_t)(wbuf * 4 + mt) * 512) * 128;
            bf16* wlo = g_hTlo + ((size_t)(wbuf * 4 + mt) * 512) * 128;
            #pragma unroll
            for (int jj = 0; jj < 4; ++jj) {
                int jl = qd * 4 + jj;
                int jg = nt * 16 + jl;
                float4 xv = xp4[jj];
                float p0 = sPr[jj * 4 + 0] + xv.x + sBq_[jj * 4 + 0];
                float p1 = sPr[jj * 4 + 1] + xv.y + sBq_[jj * 4 + 1];
                float p2 = sPr[jj * 4 + 2] + xv.z + sBq_[jj * 4 + 2];
                float p3 = sPr[jj * 4 + 3] + xv.w + sBq_[jj * 4 + 3];
                float a0 = sBqh[jl], a1 = a0, a2 = a0, a3 = a0;
                #pragma unroll
                for (int q = 0; q < NQV; q++) {
                    float w = sWqhS[q * 16 + jl];
                    a0 += zz[0][q] * w;
                    a1 += zz[1][q] * w;
                    a2 += zz[2][q] * w;
                    a3 += zz[3][q] * w;
                }
                float f  = ALPHA_F * sigm(p0)  + ALPHB_F * sigm(a0);
                float ii = ALPHA_F * sigm(p1)  + ALPHB_F * sigm(a1);
                float gg = ALPHA_F * tanhf(p2) + ALPHB_F * tanhf(a2);
                float oo = ALPHA_F * sigm(p3)  + ALPHB_F * sigm(a3);
                float cn = f * c_state[jj] + ii * gg;
                float hn = oo * tanhf(cn);
                c_state[jj] = cn;
                out[ob + jg] = hn;
                bf16 hh = __float2bfloat16_rn(hn);
                whi[(size_t)jg * 128 + r] = hh;
                wlo[(size_t)jg * 128 + r] = __float2bfloat16_rn(hn - __bfloat162float(hh));
                if (t == T_STEPS - 1 && tails) {
                    size_t outT = (size_t)T_STEPS * BATCH * HID;
                    out[outT + (size_t)rowg * HID + jg] = hn;
                    out[outT + (size_t)BATCH * HID + (size_t)rowg * HID + jg] = cn;
                }
            }
        }

        // group barrier over the 32 blocks of this mt row-group
        __syncthreads();
        if (tid == 0) {
            __threadfence();
            unsigned gen = g_genA[mt];
            if (atomicAdd(&g_arr[mt], 1u) == 31u) {
                g_arr[mt] = 0;
                __threadfence();
                g_genA[mt] = gen + 1;
            } else {
                while (g_genA[mt] == gen) { }
                __threadfence();
            }
        }
        __syncthreads();
    }
}

// ---------------- launch ------------------------------------------------------
extern "C" void kernel_launch(void* const* d_in, const int* in_sizes, int n_in,
                              void* d_out, int out_size)
{
    const float* inputs = (const float*)d_in[0];
    const float* Wf = (const float*)d_in[1];
    const float* bf_ = (const float*)d_in[2];
    const float* Wi = (const float*)d_in[3];
    const float* bi = (const float*)d_in[4];
    const float* Wu = (const float*)d_in[5];
    const float* bu = (const float*)d_in[6];
    const float* Wo = (const float*)d_in[7];
    const float* bo = (const float*)d_in[8];
    const float* Wq = (const float*)d_in[9];
    const float* bq = (const float*)d_in[10];
    const float* Wqh = (const float*)d_in[11];
    const float* bqh = (const float*)d_in[12];
    const float* th_f = (const float*)d_in[13];
    const float* th_i = (const float*)d_in[14];
    const float* th_u = (const float*)d_in[15];
    const float* th_o = (const float*)d_in[16];
    float* out = (float*)d_out;

    cudaFuncSetAttribute(gemm_x, cudaFuncAttributeMaxDynamicSharedMemorySize, 2 * GX_BUF);
    cudaFuncSetAttribute(qlstm_persistent, cudaFuncAttributeMaxDynamicSharedMemorySize, PS_TOTAL);

    const size_t outT = (size_t)T_STEPS * BATCH * HID;
    int tails = ((size_t)out_size >= outT + 2 * (size_t)BATCH * HID) ? 1 : 0;

    zero_state<<<(2 * 4 * 512 * 128 + 255) / 256, 256>>>();
    cvt_x<<<(int)(((size_t)MROWS * DIM + 255) / 256), 256>>>(inputs);
    cvt_w<<<(512 * NTOT + 255) / 256, 256>>>(Wf, Wi, Wu, Wo, bf_, bi, bu, bo);
    xq_kernel<<<MROWS / 16, 512>>>(inputs, Wq, bq);
    gemm_x<<<dim3(NTOT / 128, MROWS / 128), 256, 2 * GX_BUF>>>();
    qlstm_persistent<<<NBLOCKS, 512, PS_TOTAL>>>(
        Wq, Wqh, bqh, th_f, th_i, th_u, th_o, out, tails);
}

// round 10
// speedup vs baseline: 4.9991x; 1.4907x over previous
#include <cuda_runtime.h>
#include <cuda_bf16.h>
#include <mma.h>
#include <cstdint>

using namespace nvcuda;
typedef __nv_bfloat16 bf16;

#define T_STEPS 256
#define BATCH   512
#define DIM     512
#define HID     512
#define NQV     8
#define NTOT    2048
#define MROWS   (T_STEPS*BATCH)
#define ALPHA_F 0.7f
#define ALPHB_F 0.3f
#define NBLOCKS 128

// ---------------- device-global scratch (no allocations allowed) ------------
__device__ float g_XP[(size_t)MROWS * NTOT];      // x-part preacts (interleaved cols)
__device__ float g_XQ[(size_t)MROWS * NQV];       // x-part of q_in + bq
// X in chunk-blocked PRE-PADDED layout: [mtile(1024)][kchunk(16)][row(128)][kpad(40)]
__device__ __align__(256) bf16 g_Xhi[(size_t)1024 * 16 * 128 * 40];
__device__ __align__(256) bf16 g_Xlo[(size_t)1024 * 16 * 128 * 40];
// Wx in chunk-blocked PRE-PADDED layout: [ntile(16)][kchunk(16)][k(32)][npad(136)]
__device__ __align__(256) bf16 g_WxHi[16 * 16 * 32 * 136];
__device__ __align__(256) bf16 g_WxLo[16 * 16 * 32 * 136];
__device__ bf16  g_WhHi[512 * NTOT];              // [k][4j+g] = Wg[512+k][j] (plain)
__device__ bf16  g_WhLo[512 * NTOT];
__device__ float g_biasI[NTOT];                   // [4j+g] = b_g[j]
// h in chunk-blocked PRE-PADDED transposed layout:
// [buf][mt][col(512)][rowpad(136)]  (chunk kc = cols kc*32..kc*32+31 -> 8704B contiguous)
__device__ __align__(256) bf16 g_hThi[2 * 4 * 512 * 136];
__device__ __align__(256) bf16 g_hTlo[2 * 4 * 512 * 136];
__device__ unsigned g_arr[4];
__device__ volatile unsigned g_genA[4];

__device__ __forceinline__ float sigm(float x) { return 1.f / (1.f + expf(-x)); }

// ---- bulk async copy + mbarrier helpers (sm_90+) ----
__device__ __forceinline__ void bulk_cp(unsigned dst_s, const void* src, unsigned bytes, unsigned mbar_s) {
    asm volatile("cp.async.bulk.shared::cta.global.mbarrier::complete_tx::bytes [%0], [%1], %2, [%3];"
                 :: "r"(dst_s), "l"(src), "r"(bytes), "r"(mbar_s) : "memory");
}
__device__ __forceinline__ void mbar_init(unsigned mbar_s, unsigned cnt) {
    asm volatile("mbarrier.init.shared.b64 [%0], %1;" :: "r"(mbar_s), "r"(cnt) : "memory");
}
__device__ __forceinline__ void mbar_expect(unsigned mbar_s, unsigned bytes) {
    asm volatile("mbarrier.arrive.expect_tx.shared.b64 _, [%0], %1;" :: "r"(mbar_s), "r"(bytes) : "memory");
}
__device__ __forceinline__ void mbar_wait(unsigned mbar_s, unsigned parity) {
    asm volatile(
        "{\n\t.reg .pred P;\n"
        "LW_%=:\n\t"
        "mbarrier.try_wait.parity.acquire.cta.shared::cta.b64 P, [%0], %1, 0x989680;\n\t"
        "@P bra LD_%=;\n\t"
        "bra LW_%=;\n"
        "LD_%=:\n\t}"
        :: "r"(mbar_s), "r"(parity) : "memory");
}

// ---------------- init: zero h buffers + barrier state -----------------------
__global__ void zero_state() {
    int i = blockIdx.x * blockDim.x + threadIdx.x;
    if (i < 2 * 4 * 512 * 136) {
        g_hThi[i] = __float2bfloat16(0.f);
        g_hTlo[i] = __float2bfloat16(0.f);
    }
    if (i < 4) { g_arr[i] = 0; g_genA[i] = 0; }
}

// ---------------- split inputs into bf16 hi/lo (chunk-blocked padded) ---------
__global__ void cvt_x(const float* __restrict__ x) {
    size_t i = (size_t)blockIdx.x * blockDim.x + threadIdx.x;
    if (i >= (size_t)MROWS * DIM) return;
    size_t m = i >> 9;
    int k = (int)(i & 511);
    int mtile = (int)(m >> 7), r = (int)(m & 127);
    int kc = k >> 5, kk = k & 31;
    size_t dst = (((size_t)mtile * 16 + kc) * 128 + r) * 40 + kk;
    float v = x[i];
    bf16 h = __float2bfloat16_rn(v);
    g_Xhi[dst] = h;
    g_Xlo[dst] = __float2bfloat16_rn(v - __bfloat162float(h));
}

// ---------------- build interleaved split weights + bias ----------------------
__global__ void cvt_w(const float* __restrict__ w0, const float* __restrict__ w1,
                      const float* __restrict__ w2, const float* __restrict__ w3,
                      const float* __restrict__ b0, const float* __restrict__ b1,
                      const float* __restrict__ b2, const float* __restrict__ b3) {
    int i = blockIdx.x * blockDim.x + threadIdx.x;
    if (i >= 512 * NTOT) return;
    int k = i >> 11, np = i & (NTOT - 1);
    int j = np >> 2, g = np & 3;
    const float* W = (g == 0) ? w0 : (g == 1) ? w1 : (g == 2) ? w2 : w3;
    float vx = W[(size_t)k * 512 + j];
    float vh = W[(size_t)(512 + k) * 512 + j];
    // Wx: chunk-blocked padded layout
    int ntile = np >> 7, n = np & 127, kc = k >> 5, kk = k & 31;
    size_t wdst = (((size_t)ntile * 16 + kc) * 32 + kk) * 136 + n;
    bf16 hx = __float2bfloat16_rn(vx);
    g_WxHi[wdst] = hx;
    g_WxLo[wdst] = __float2bfloat16_rn(vx - __bfloat162float(hx));
    // Wh: plain layout (loaded once into persistent smem)
    bf16 hh = __float2bfloat16_rn(vh);
    g_WhHi[i] = hh;
    g_WhLo[i] = __float2bfloat16_rn(vh - __bfloat162float(hh));
    if (k == 0) {
        const float* B = (g == 0) ? b0 : (g == 1) ? b1 : (g == 2) ? b2 : b3;
        g_biasI[np] = B[j];
    }
}

// ---------------- XQ = inputs @ Wq[0:512] + bq -------------------------------
__global__ void __launch_bounds__(512) xq_kernel(
    const float* __restrict__ inputs, const float* __restrict__ Wq,
    const float* __restrict__ bq)
{
    __shared__ float sWq[NQV * 513];
    __shared__ float sBq[NQV];
    int tid = threadIdx.x;
    for (int i = tid; i < 512 * NQV; i += 512) {
        int k = i >> 3, q = i & 7;
        sWq[q * 513 + k] = Wq[(size_t)k * NQV + q];
    }
    if (tid < NQV) sBq[tid] = bq[tid];
    __syncthreads();

    int gw   = blockIdx.x * 16 + (tid >> 5);
    int lane = tid & 31;
    const float* x = inputs + (size_t)gw * DIM;
    float acc[NQV];
    #pragma unroll
    for (int q = 0; q < NQV; q++) acc[q] = 0.f;
    #pragma unroll 4
    for (int k = lane; k < DIM; k += 32) {
        float xv = x[k];
        #pragma unroll
        for (int q = 0; q < NQV; q++) acc[q] += xv * sWq[q * 513 + k];
    }
    #pragma unroll
    for (int q = 0; q < NQV; q++) {
        float v = acc[q];
        #pragma unroll
        for (int off = 16; off; off >>= 1) v += __shfl_xor_sync(0xffffffffu, v, off);
        acc[q] = v;
    }
    if (lane == 0) {
        #pragma unroll
        for (int q = 0; q < NQV; q++) g_XQ[(size_t)gw * NQV + q] = acc[q] + sBq[q];
    }
}

// ---------------- precompute GEMM: XP = Xsplit @ Wx' (bf16x3, bulk-TMA) -------
#define GA_LD 40
#define GB_LD 136
#define GXS_AHI 0
#define GXS_ALO 10240
#define GXS_BHI 20480
#define GXS_BLO 29184
#define GXS_SZ  37888
#define GXS_MB  (3 * GXS_SZ)            // 113664
#define GX_TOTAL (GXS_MB + 128)
__global__ void __launch_bounds__(256, 2) gemm_x()
{
    extern __shared__ char smem[];
    const unsigned su = (unsigned)__cvta_generic_to_shared(smem);
    const int tid = threadIdx.x;
    const int ntile = blockIdx.x;        // 16
    const int mtile = blockIdx.y;        // 1024
    const int n0 = ntile * 128;
    const size_t m0 = (size_t)mtile * 128;

    const int warp = tid >> 5;
    const int wr = warp & 3;
    const int wc = warp >> 2;

    if (tid == 0) {
        #pragma unroll
        for (int s = 0; s < 3; ++s) mbar_init(su + GXS_MB + s * 8, 1);
    }
    __syncthreads();
    int ph[3] = {0, 0, 0};

    wmma::fragment<wmma::accumulator, 16, 16, 16, float> acc[2][4];
    #pragma unroll
    for (int i = 0; i < 2; i++)
        #pragma unroll
        for (int j = 0; j < 4; j++) wmma::fill_fragment(acc[i][j], 0.f);

    auto issue = [&](int kc) {
        if (tid == 0) {
            int s = kc % 3;
            unsigned mb = su + GXS_MB + s * 8;
            mbar_expect(mb, GXS_SZ);
            unsigned d = su + s * GXS_SZ;
            bulk_cp(d + GXS_AHI, g_Xhi + ((size_t)mtile * 16 + kc) * 5120, 10240, mb);
            bulk_cp(d + GXS_ALO, g_Xlo + ((size_t)mtile * 16 + kc) * 5120, 10240, mb);
            bulk_cp(d + GXS_BHI, g_WxHi + ((size_t)ntile * 16 + kc) * 4352, 8704, mb);
            bulk_cp(d + GXS_BLO, g_WxLo + ((size_t)ntile * 16 + kc) * 4352, 8704, mb);
        }
    };

    issue(0); issue(1);
    for (int kc = 0; kc < 16; ++kc) {
        if (kc < 14) issue(kc + 2);
        int s = kc % 3;
        mbar_wait(su + GXS_MB + s * 8, ph[s]); ph[s] ^= 1;

        char* base = smem + s * GXS_SZ;
        const bf16* Ahi = (const bf16*)(base + GXS_AHI);
        const bf16* Alo = (const bf16*)(base + GXS_ALO);
        const bf16* Bhi = (const bf16*)(base + GXS_BHI);
        const bf16* Blo = (const bf16*)(base + GXS_BLO);
        #pragma unroll
        for (int ks = 0; ks < 2; ++ks) {
            wmma::fragment<wmma::matrix_a, 16, 16, 16, bf16, wmma::row_major> ahi[2], alo[2];
            wmma::fragment<wmma::matrix_b, 16, 16, 16, bf16, wmma::row_major> bhi[4], blo[4];
            #pragma unroll
            for (int i = 0; i < 2; i++) {
                wmma::load_matrix_sync(ahi[i], Ahi + (wr * 32 + i * 16) * GA_LD + ks * 16, GA_LD);
                wmma::load_matrix_sync(alo[i], Alo + (wr * 32 + i * 16) * GA_LD + ks * 16, GA_LD);
            }
            #pragma unroll
            for (int j = 0; j < 4; j++) {
                wmma::load_matrix_sync(bhi[j], Bhi + (ks * 16) * GB_LD + wc * 64 + j * 16, GB_LD);
                wmma::load_matrix_sync(blo[j], Blo + (ks * 16) * GB_LD + wc * 64 + j * 16, GB_LD);
            }
            #pragma unroll
            for (int i = 0; i < 2; i++)
                #pragma unroll
                for (int j = 0; j < 4; j++) {
                    wmma::mma_sync(acc[i][j], ahi[i], bhi[j], acc[i][j]);
                    wmma::mma_sync(acc[i][j], ahi[i], blo[j], acc[i][j]);
                    wmma::mma_sync(acc[i][j], alo[i], bhi[j], acc[i][j]);
                }
        }
        __syncthreads();
    }
    #pragma unroll
    for (int i = 0; i < 2; i++)
        #pragma unroll
        for (int j = 0; j < 4; j++) {
            size_t row0 = m0 + wr * 32 + i * 16;
            int    col0 = n0 + wc * 64 + j * 16;
            wmma::store_matrix_sync(g_XP + row0 * NTOT + col0, acc[i][j], NTOT, wmma::mem_row_major);
        }
}

// ---------------- persistent recurrent kernel --------------------------------
// smem map (bytes):
#define SW_HI   0         // 512 x 72 bf16 = 73728
#define SW_LO   73728
#define SQW     147456    // 512 x 24 bf16 = 24576 (cols 0-7 WqH hi, 8-15 WqH lo)
#define ST_A    172032    // 3 stages x 17408 (hi 32x136 bf16, lo at +8704)
#define ST_ABUF 17408
#define SBIAS   224256    // 64 f32
#define SWQHS   224512    // 8 x 16 f32
#define SBQH    225024    // 16 f32
#define STH     225088    // 32 f32
#define SMB     225216    // 3 mbarriers
#define PS_TOTAL 225280
// epilogue alias over ST_A: sP 128 x 68 f32 = 34816 (covers stages 0-1),
//                           sQm 128 x 16 f32 = 8192 at ST_A+34816 (in stage 2)

#define W_LD  72
#define QW_LD 24
#define A_LD  136
#define SP_LD 68

__global__ void __launch_bounds__(512) qlstm_persistent(
    const float* __restrict__ Wq,  const float* __restrict__ Wqh,
    const float* __restrict__ bqh,
    const float* __restrict__ thf, const float* __restrict__ thi,
    const float* __restrict__ thu, const float* __restrict__ tho,
    float* __restrict__ out, int tails)
{
    extern __shared__ char smem[];
    const unsigned smem_u = (unsigned)__cvta_generic_to_shared(smem);
    const int tid = threadIdx.x;
    const int bx = blockIdx.x;
    const int mt = bx >> 5, nt = bx & 31;
    const int m0 = mt * 128;
    const int nc0 = nt * 64;
    const int warp = tid >> 5;
    const int wr = warp >> 1;            // 0..7 : 16 rows each
    const int wc = warp & 1;             // 0..1 : 32 cols each

    bf16* sWhi = (bf16*)(smem + SW_HI);
    bf16* sWlo = (bf16*)(smem + SW_LO);
    for (int i = tid; i < 512 * 64; i += 512) {
        int k = i >> 6, n = i & 63;
        sWhi[k * W_LD + n] = g_WhHi[(size_t)k * NTOT + nc0 + n];
        sWlo[k * W_LD + n] = g_WhLo[(size_t)k * NTOT + nc0 + n];
    }
    bf16* sQW = (bf16*)(smem + SQW);
    for (int i = tid; i < 512 * 16; i += 512) {
        int k = i >> 4, c = i & 15;
        float v = Wq[(size_t)(512 + k) * NQV + (c & 7)];
        bf16 h = __float2bfloat16_rn(v);
        sQW[k * QW_LD + c] = (c < 8) ? h : __float2bfloat16_rn(v - __bfloat162float(h));
    }
    float* sBias = (float*)(smem + SBIAS);
    if (tid < 64) sBias[tid] = g_biasI[nc0 + tid];
    float* sWqhS = (float*)(smem + SWQHS);
    if (tid < 128) sWqhS[tid] = Wqh[(size_t)(tid >> 4) * HID + nt * 16 + (tid & 15)];
    float* sBqh = (float*)(smem + SBQH);
    if (tid < 16) sBqh[tid] = bqh[nt * 16 + tid];
    float* sTh = (float*)(smem + STH);
    if (tid < 32) {
        int g = tid >> 3, q = tid & 7;
        sTh[tid] = (g == 0) ? thf[q] : (g == 1) ? thi[q] : (g == 2) ? thu[q] : tho[q];
    }
    if (tid == 0) {
        #pragma unroll
        for (int s = 0; s < 3; ++s) mbar_init(smem_u + SMB + s * 8, 1);
    }
    float c_state[4];
    #pragma unroll
    for (int i = 0; i < 4; i++) c_state[i] = 0.f;
    __syncthreads();

    int ph[3] = {0, 0, 0};

    for (int t = 0; t < T_STEPS; ++t) {
        const int rbuf = t & 1, wbuf = rbuf ^ 1;
        const bf16* hHiT = g_hThi + (size_t)(rbuf * 4 + mt) * (512 * 136);
        const bf16* hLoT = g_hTlo + (size_t)(rbuf * 4 + mt) * (512 * 136);

        wmma::fragment<wmma::accumulator, 16, 16, 16, float> acch[2], accx[2], accq;
        #pragma unroll
        for (int j = 0; j < 2; j++) { wmma::fill_fragment(acch[j], 0.f); wmma::fill_fragment(accx[j], 0.f); }
        wmma::fill_fragment(accq, 0.f);

        auto issue_chunk = [&](int kc) {
            if (tid == 0) {
                int s = kc % 3;
                unsigned mb = smem_u + SMB + s * 8;
                mbar_expect(mb, 2 * 8704);
                unsigned d = smem_u + ST_A + s * ST_ABUF;
                bulk_cp(d,        hHiT + (size_t)kc * 4352, 8704, mb);
                bulk_cp(d + 8704, hLoT + (size_t)kc * 4352, 8704, mb);
            }
        };

        issue_chunk(0); issue_chunk(1);
        for (int kc = 0; kc < 16; ++kc) {
            if (kc < 14) issue_chunk(kc + 2);
            int s = kc % 3;
            mbar_wait(smem_u + SMB + s * 8, ph[s]); ph[s] ^= 1;

            const bf16* Ahi = (const bf16*)(smem + ST_A + s * ST_ABUF);
            const bf16* Alo = (const bf16*)(smem + ST_A + s * ST_ABUF + 8704);
            const int kb = kc * 32;
            #pragma unroll
            for (int ks = 0; ks < 2; ++ks) {
                wmma::fragment<wmma::matrix_a, 16, 16, 16, bf16, wmma::col_major> ahi, alo;
                wmma::load_matrix_sync(ahi, Ahi + (ks * 16) * A_LD + wr * 16, A_LD);
                wmma::load_matrix_sync(alo, Alo + (ks * 16) * A_LD + wr * 16, A_LD);
                #pragma unroll
                for (int j = 0; j < 2; j++) {
                    wmma::fragment<wmma::matrix_b, 16, 16, 16, bf16, wmma::row_major> bhi, blo;
                    wmma::load_matrix_sync(bhi, sWhi + (kb + ks * 16) * W_LD + wc * 32 + j * 16, W_LD);
                    wmma::load_matrix_sync(blo, sWlo + (kb + ks * 16) * W_LD + wc * 32 + j * 16, W_LD);
                    wmma::mma_sync(acch[j], ahi, bhi, acch[j]);
                    wmma::mma_sync(accx[j], ahi, blo, accx[j]);
                    wmma::mma_sync(accx[j], alo, bhi, accx[j]);
                }
                if (wc == 0) {
                    wmma::fragment<wmma::matrix_b, 16, 16, 16, bf16, wmma::row_major> bq;
                    wmma::load_matrix_sync(bq, sQW + (kb + ks * 16) * QW_LD, QW_LD);
                    wmma::mma_sync(accq, ahi, bq, accq);
                    wmma::mma_sync(accq, alo, bq, accq);
                }
            }
            __syncthreads();
        }

        // --- epilogue: store preacts + q into smem (stages are free now) ---
        float* sP  = (float*)(smem + ST_A);
        float* sQm = (float*)(smem + ST_A + 34816);
        #pragma unroll
        for (int j = 0; j < 2; j++) {
            #pragma unroll
            for (int e = 0; e < acch[j].num_elements; ++e) acch[j].x[e] += accx[j].x[e];
            wmma::store_matrix_sync(sP + (wr * 16) * SP_LD + wc * 32 + j * 16, acch[j], SP_LD, wmma::mem_row_major);
        }
        if (wc == 0)
            wmma::store_matrix_sync(sQm + (wr * 16) * 16, accq, 16, wmma::mem_row_major);
        __syncthreads();

        // phase1: thread = (row, gate): qin + cumprod(cos) -> z[8] in regs
        const int r = tid >> 2;
        const int gq = tid & 3;
        float z[NQV];
        {
            const float* xq = g_XQ + ((size_t)t * BATCH + m0 + r) * NQV;
            float run = 1.f;
            #pragma unroll
            for (int q = 0; q < NQV; ++q) {
                float qin = sQm[r * 16 + q] + sQm[r * 16 + 8 + q] + xq[q];
                run *= __cosf(qin + sTh[gq * 8 + q]);
                z[q] = run;
            }
        }
        // exchange z across the 4 lanes of this row (same warp)
        float zz[4][NQV];
        {
            const int lb = (tid & 31) & ~3;
            #pragma unroll
            for (int g = 0; g < 4; ++g)
                #pragma unroll
                for (int q = 0; q < NQV; ++q)
                    zz[g][q] = __shfl_sync(0xffffffffu, z[q], lb + g);
        }

        // phase2: thread = (row, col-quad): gate combine + LSTM update
        {
            const int qd = gq;
            const int rowg = m0 + r;
            const float4* xp4 = (const float4*)(g_XP + ((size_t)t * BATCH + rowg) * NTOT + nc0 + qd * 16);
            const float* sPr = sP + r * SP_LD + qd * 16;
            const float* sBq_ = sBias + qd * 16;
            const size_t ob = ((size_t)t * BATCH + rowg) * HID;
            bf16* whi = g_hThi + (size_t)(wbuf * 4 + mt) * (512 * 136);
            bf16* wlo = g_hTlo + (size_t)(wbuf * 4 + mt) * (512 * 136);
            #pragma unroll
            for (int jj = 0; jj < 4; ++jj) {
                int jl = qd * 4 + jj;
                int jg = nt * 16 + jl;
                float4 xv = xp4[jj];
                float p0 = sPr[jj * 4 + 0] + xv.x + sBq_[jj * 4 + 0];
                float p1 = sPr[jj * 4 + 1] + xv.y + sBq_[jj * 4 + 1];
                float p2 = sPr[jj * 4 + 2] + xv.z + sBq_[jj * 4 + 2];
                float p3 = sPr[jj * 4 + 3] + xv.w + sBq_[jj * 4 + 3];
                float a0 = sBqh[jl], a1 = a0, a2 = a0, a3 = a0;
                #pragma unroll
                for (int q = 0; q < NQV; q++) {
                    float w = sWqhS[q * 16 + jl];
                    a0 += zz[0][q] * w;
                    a1 += zz[1][q] * w;
                    a2 += zz[2][q] * w;
                    a3 += zz[3][q] * w;
                }
                float f  = ALPHA_F * sigm(p0)  + ALPHB_F * sigm(a0);
                float ii = ALPHA_F * sigm(p1)  + ALPHB_F * sigm(a1);
                float gg = ALPHA_F * tanhf(p2) + ALPHB_F * tanhf(a2);
                float oo = ALPHA_F * sigm(p3)  + ALPHB_F * sigm(a3);
                float cn = f * c_state[jj] + ii * gg;
                float hn = oo * tanhf(cn);
                c_state[jj] = cn;
                out[ob + jg] = hn;
                bf16 hh = __float2bfloat16_rn(hn);
                whi[(size_t)jg * 136 + r] = hh;
                wlo[(size_t)jg * 136 + r] = __float2bfloat16_rn(hn - __bfloat162float(hh));
                if (t == T_STEPS - 1 && tails) {
                    size_t outT = (size_t)T_STEPS * BATCH * HID;
                    out[outT + (size_t)rowg * HID + jg] = hn;
                    out[outT + (size_t)BATCH * HID + (size_t)rowg * HID + jg] = cn;
                }
            }
        }

        // group barrier over the 32 blocks of this mt row-group
        __syncthreads();
        if (tid == 0) {
            __threadfence();
            unsigned gen = g_genA[mt];
            if (atomicAdd(&g_arr[mt], 1u) == 31u) {
                g_arr[mt] = 0;
                __threadfence();
                g_genA[mt] = gen + 1;
            } else {
                while (g_genA[mt] == gen) { }
                __threadfence();
            }
        }
        __syncthreads();
    }
}

// ---------------- launch ------------------------------------------------------
extern "C" void kernel_launch(void* const* d_in, const int* in_sizes, int n_in,
                              void* d_out, int out_size)
{
    const float* inputs = (const float*)d_in[0];
    const float* Wf = (const float*)d_in[1];
    const float* bf_ = (const float*)d_in[2];
    const float* Wi = (const float*)d_in[3];
    const float* bi = (const float*)d_in[4];
    const float* Wu = (const float*)d_in[5];
    const float* bu = (const float*)d_in[6];
    const float* Wo = (const float*)d_in[7];
    const float* bo = (const float*)d_in[8];
    const float* Wq = (const float*)d_in[9];
    const float* bq = (const float*)d_in[10];
    const float* Wqh = (const float*)d_in[11];
    const float* bqh = (const float*)d_in[12];
    const float* th_f = (const float*)d_in[13];
    const float* th_i = (const float*)d_in[14];
    const float* th_u = (const float*)d_in[15];
    const float* th_o = (const float*)d_in[16];
    float* out = (float*)d_out;

    cudaFuncSetAttribute(gemm_x, cudaFuncAttributeMaxDynamicSharedMemorySize, GX_TOTAL);
    cudaFuncSetAttribute(qlstm_persistent, cudaFuncAttributeMaxDynamicSharedMemorySize, PS_TOTAL);

    const size_t outT = (size_t)T_STEPS * BATCH * HID;
    int tails = ((size_t)out_size >= outT + 2 * (size_t)BATCH * HID) ? 1 : 0;

    zero_state<<<(2 * 4 * 512 * 136 + 255) / 256, 256>>>();
    cvt_x<<<(int)(((size_t)MROWS * DIM + 255) / 256), 256>>>(inputs);
    cvt_w<<<(512 * NTOT + 255) / 256, 256>>>(Wf, Wi, Wu, Wo, bf_, bi, bu, bo);
    xq_kernel<<<MROWS / 16, 512>>>(inputs, Wq, bq);
    gemm_x<<<dim3(16, MROWS / 128), 256, GX_TOTAL>>>();
    qlstm_persistent<<<NBLOCKS, 512, PS_TOTAL>>>(
        Wq, Wqh, bqh, th_f, th_i, th_u, th_o, out, tails);
}

// round 12
// speedup vs baseline: 5.3711x; 1.0744x over previous
#include <cuda_runtime.h>
#include <cuda_bf16.h>
#include <mma.h>
#include <cstdint>

using namespace nvcuda;
typedef __nv_bfloat16 bf16;

#define T_STEPS 256
#define BATCH   512
#define DIM     512
#define HID     512
#define NQV     8
#define NTOT    2048
#define MROWS   (T_STEPS*BATCH)
#define ALPHA_F 0.7f
#define ALPHB_F 0.3f
#define NBLOCKS 128

// ---------------- device-global scratch (no allocations allowed) ------------
__device__ float g_XP[(size_t)MROWS * NTOT];      // x-part preacts (interleaved cols)
__device__ float g_XQ[(size_t)MROWS * NQV];       // x-part of q_in + bq
// X fused hi|lo chunk blocks: [mtile(1024)][kchunk(16)]{hi 128x40 | lo 128x40} bf16
__device__ __align__(256) bf16 g_Xc[(size_t)1024 * 16 * 10240];
// Wx fused hi|lo chunk blocks: [ntile(16)][kchunk(16)]{hi 32x136 | lo 32x136} bf16
__device__ __align__(256) bf16 g_Wxc[16 * 16 * 8704];
__device__ bf16  g_WhHi[512 * NTOT];              // [k][4j+g] = Wg[512+k][j] (plain)
__device__ bf16  g_WhLo[512 * NTOT];
__device__ float g_biasI[NTOT];                   // [4j+g] = b_g[j]
// h fused hi|lo chunk blocks (pre-padded A-tile images):
// [buf(2)][mt(4)][kc(16)]{hi col(32)x136row | lo col(32)x136row} bf16 = 17408B/chunk
__device__ __align__(256) bf16 g_hT[2 * 4 * 16 * 8704];
__device__ unsigned g_arr[4];
__device__ volatile unsigned g_genA[4];

__device__ __forceinline__ float sigm(float x) { return 1.f / (1.f + expf(-x)); }

// ---- bulk async copy + mbarrier helpers (baseline sm_90 PTX, ok on compute_103) ----
__device__ __forceinline__ void bulk_cp(unsigned dst_s, const void* src, unsigned bytes, unsigned mbar_s) {
    asm volatile("cp.async.bulk.shared::cta.global.mbarrier::complete_tx::bytes [%0], [%1], %2, [%3];"
                 :: "r"(dst_s), "l"(src), "r"(bytes), "r"(mbar_s) : "memory");
}
__device__ __forceinline__ void mbar_init(unsigned mbar_s, unsigned cnt) {
    asm volatile("mbarrier.init.shared.b64 [%0], %1;" :: "r"(mbar_s), "r"(cnt) : "memory");
}
__device__ __forceinline__ void mbar_expect(unsigned mbar_s, unsigned bytes) {
    asm volatile("mbarrier.arrive.expect_tx.shared.b64 _, [%0], %1;" :: "r"(mbar_s), "r"(bytes) : "memory");
}
__device__ __forceinline__ void mbar_arrive(unsigned mbar_s) {
    asm volatile("mbarrier.arrive.shared.b64 _, [%0];" :: "r"(mbar_s) : "memory");
}
__device__ __forceinline__ void mbar_wait(unsigned mbar_s, unsigned parity) {
    asm volatile(
        "{\n\t.reg .pred P;\n"
        "LW_%=:\n\t"
        "mbarrier.try_wait.parity.acquire.cta.shared::cta.b64 P, [%0], %1, 0x989680;\n\t"
        "@P bra LD_%=;\n\t"
        "bra LW_%=;\n"
        "LD_%=:\n\t}"
        :: "r"(mbar_s), "r"(parity) : "memory");
}
#define FENCE_ASYNC() asm volatile("fence.proxy.async.shared::cta;" ::: "memory")

// ---------------- init: zero h buffer + barrier state ------------------------
__global__ void zero_state() {
    int i = blockIdx.x * blockDim.x + threadIdx.x;
    if (i < 2 * 4 * 16 * 8704) g_hT[i] = __float2bfloat16(0.f);
    if (i < 4) { g_arr[i] = 0; g_genA[i] = 0; }
}

// ---------------- split inputs into fused hi|lo chunk blocks ------------------
__global__ void cvt_x(const float* __restrict__ x) {
    size_t i = (size_t)blockIdx.x * blockDim.x + threadIdx.x;
    if (i >= (size_t)MROWS * DIM) return;
    size_t m = i >> 9;
    int k = (int)(i & 511);
    int mtile = (int)(m >> 7), r = (int)(m & 127);
    int kc = k >> 5, kk = k & 31;
    size_t base = (size_t)(mtile * 16 + kc) * 10240 + (size_t)r * 40 + kk;
    float v = x[i];
    bf16 h = __float2bfloat16_rn(v);
    g_Xc[base] = h;
    g_Xc[base + 5120] = __float2bfloat16_rn(v - __bfloat162float(h));
}

// ---------------- build interleaved split weights + bias ----------------------
__global__ void cvt_w(const float* __restrict__ w0, const float* __restrict__ w1,
                      const float* __restrict__ w2, const float* __restrict__ w3,
                      const float* __restrict__ b0, const float* __restrict__ b1,
                      const float* __restrict__ b2, const float* __restrict__ b3) {
    int i = blockIdx.x * blockDim.x + threadIdx.x;
    if (i >= 512 * NTOT) return;
    int k = i >> 11, np = i & (NTOT - 1);
    int j = np >> 2, g = np & 3;
    const float* W = (g == 0) ? w0 : (g == 1) ? w1 : (g == 2) ? w2 : w3;
    float vx = W[(size_t)k * 512 + j];
    float vh = W[(size_t)(512 + k) * 512 + j];
    int ntile = np >> 7, n = np & 127, kc = k >> 5, kk = k & 31;
    size_t wb = (size_t)(ntile * 16 + kc) * 8704 + (size_t)kk * 136 + n;
    bf16 hx = __float2bfloat16_rn(vx);
    g_Wxc[wb] = hx;
    g_Wxc[wb + 4352] = __float2bfloat16_rn(vx - __bfloat162float(hx));
    bf16 hh = __float2bfloat16_rn(vh);
    g_WhHi[i] = hh;
    g_WhLo[i] = __float2bfloat16_rn(vh - __bfloat162float(hh));
    if (k == 0) {
        const float* B = (g == 0) ? b0 : (g == 1) ? b1 : (g == 2) ? b2 : b3;
        g_biasI[np] = B[j];
    }
}

// ---------------- XQ = inputs @ Wq[0:512] + bq -------------------------------
__global__ void __launch_bounds__(512) xq_kernel(
    const float* __restrict__ inputs, const float* __restrict__ Wq,
    const float* __restrict__ bq)
{
    __shared__ float sWq[NQV * 513];
    __shared__ float sBq[NQV];
    int tid = threadIdx.x;
    for (int i = tid; i < 512 * NQV; i += 512) {
        int k = i >> 3, q = i & 7;
        sWq[q * 513 + k] = Wq[(size_t)k * NQV + q];
    }
    if (tid < NQV) sBq[tid] = bq[tid];
    __syncthreads();

    int gw   = blockIdx.x * 16 + (tid >> 5);
    int lane = tid & 31;
    const float* x = inputs + (size_t)gw * DIM;
    float acc[NQV];
    #pragma unroll
    for (int q = 0; q < NQV; q++) acc[q] = 0.f;
    #pragma unroll 4
    for (int k = lane; k < DIM; k += 32) {
        float xv = x[k];
        #pragma unroll
        for (int q = 0; q < NQV; q++) acc[q] += xv * sWq[q * 513 + k];
    }
    #pragma unroll
    for (int q = 0; q < NQV; q++) {
        float v = acc[q];
        #pragma unroll
        for (int off = 16; off; off >>= 1) v += __shfl_xor_sync(0xffffffffu, v, off);
        acc[q] = v;
    }
    if (lane == 0) {
        #pragma unroll
        for (int q = 0; q < NQV; q++) g_XQ[(size_t)gw * NQV + q] = acc[q] + sBq[q];
    }
}

// ---------------- precompute GEMM: XP = Xsplit @ Wx' (bf16x3, bulk-TMA) -------
#define GA_LD 40
#define GB_LD 136
#define GXS_AHI 0
#define GXS_ALO 10240
#define GXS_BHI 20480
#define GXS_BLO 29184
#define GXS_SZ  37888
#define GXS_MB  (3 * GXS_SZ)
#define GX_TOTAL (GXS_MB + 128)
__global__ void __launch_bounds__(256, 2) gemm_x()
{
    extern __shared__ char smem[];
    const unsigned su = (unsigned)__cvta_generic_to_shared(smem);
    const int tid = threadIdx.x;
    const int ntile = blockIdx.x;
    const int mtile = blockIdx.y;
    const int n0 = ntile * 128;
    const size_t m0 = (size_t)mtile * 128;

    const int warp = tid >> 5;
    const int wr = warp & 3;
    const int wc = warp >> 2;

    if (tid == 0) {
        #pragma unroll
        for (int s = 0; s < 3; ++s) mbar_init(su + GXS_MB + s * 8, 1);
    }
    __syncthreads();
    int ph[3] = {0, 0, 0};

    wmma::fragment<wmma::accumulator, 16, 16, 16, float> acc[2][4];
    #pragma unroll
    for (int i = 0; i < 2; i++)
        #pragma unroll
        for (int j = 0; j < 4; j++) wmma::fill_fragment(acc[i][j], 0.f);

    auto issue = [&](int kc) {
        if (tid == 0) {
            int s = kc % 3;
            unsigned mb = su + GXS_MB + s * 8;
            mbar_expect(mb, GXS_SZ);
            unsigned d = su + s * GXS_SZ;
            bulk_cp(d + GXS_AHI, g_Xc  + ((size_t)mtile * 16 + kc) * 10240, 20480, mb);
            bulk_cp(d + GXS_BHI, g_Wxc + ((size_t)ntile * 16 + kc) * 8704,  17408, mb);
        }
    };

    issue(0); issue(1);
    for (int kc = 0; kc < 16; ++kc) {
        if (kc < 14) issue(kc + 2);
        int s = kc % 3;
        mbar_wait(su + GXS_MB + s * 8, ph[s]); ph[s] ^= 1;

        char* base = smem + s * GXS_SZ;
        const bf16* Ahi = (const bf16*)(base + GXS_AHI);
        const bf16* Alo = (const bf16*)(base + GXS_ALO);
        const bf16* Bhi = (const bf16*)(base + GXS_BHI);
        const bf16* Blo = (const bf16*)(base + GXS_BLO);
        #pragma unroll
        for (int ks = 0; ks < 2; ++ks) {
            wmma::fragment<wmma::matrix_a, 16, 16, 16, bf16, wmma::row_major> ahi[2], alo[2];
            wmma::fragment<wmma::matrix_b, 16, 16, 16, bf16, wmma::row_major> bhi[4], blo[4];
            #pragma unroll
            for (int i = 0; i < 2; i++) {
                wmma::load_matrix_sync(ahi[i], Ahi + (wr * 32 + i * 16) * GA_LD + ks * 16, GA_LD);
                wmma::load_matrix_sync(alo[i], Alo + (wr * 32 + i * 16) * GA_LD + ks * 16, GA_LD);
            }
            #pragma unroll
            for (int j = 0; j < 4; j++) {
                wmma::load_matrix_sync(bhi[j], Bhi + (ks * 16) * GB_LD + wc * 64 + j * 16, GB_LD);
                wmma::load_matrix_sync(blo[j], Blo + (ks * 16) * GB_LD + wc * 64 + j * 16, GB_LD);
            }
            #pragma unroll
            for (int i = 0; i < 2; i++)
                #pragma unroll
                for (int j = 0; j < 4; j++) {
                    wmma::mma_sync(acc[i][j], ahi[i], bhi[j], acc[i][j]);
                    wmma::mma_sync(acc[i][j], ahi[i], blo[j], acc[i][j]);
                    wmma::mma_sync(acc[i][j], alo[i], bhi[j], acc[i][j]);
                }
        }
        __syncthreads();
    }
    #pragma unroll
    for (int i = 0; i < 2; i++)
        #pragma unroll
        for (int j = 0; j < 4; j++) {
            size_t row0 = m0 + wr * 32 + i * 16;
            int    col0 = n0 + wc * 64 + j * 16;
            wmma::store_matrix_sync(g_XP + row0 * NTOT + col0, acc[i][j], NTOT, wmma::mem_row_major);
        }
}

// ---------------- persistent recurrent kernel (warp-specialized producer) -----
#define SW_HI   0         // 512 x 72 bf16 = 73728
#define SW_LO   73728
#define SQW     147456    // 512 x 24 bf16 = 24576 (cols 0-7 WqH hi, 8-15 WqH lo)
#define ST_A    172032    // 3 stages x 17408 (hi 32x136 bf16, lo at +8704)
#define ST_ABUF 17408
#define SBIAS   224256
#define SWQHS   224512
#define SBQH    225024
#define STH     225088
#define SMB_FULL 225216   // 3 full barriers
#define SMB_CONS 225240   // 3 consumed barriers (count=16)
#define PS_TOTAL 225280
// epilogue alias over ST_A: sP 128x68 f32 (34816B, stages 0-1), sQm @+34816 (stage 2)

#define W_LD  72
#define QW_LD 24
#define A_LD  136
#define SP_LD 68

__global__ void __launch_bounds__(544) qlstm_persistent(
    const float* __restrict__ Wq,  const float* __restrict__ Wqh,
    const float* __restrict__ bqh,
    const float* __restrict__ thf, const float* __restrict__ thi,
    const float* __restrict__ thu, const float* __restrict__ tho,
    float* __restrict__ out, int tails)
{
    extern __shared__ char smem[];
    const unsigned su = (unsigned)__cvta_generic_to_shared(smem);
    const int tid = threadIdx.x;
    const int bx = blockIdx.x;
    const int mt = bx >> 5, nt = bx & 31;
    const int m0 = mt * 128;
    const int nc0 = nt * 64;
    const int warp = tid >> 5;
    const int lane = tid & 31;
    const int wr = warp >> 1;            // 0..7 : 16 rows each (consumer warps)
    const int wc = warp & 1;             // 0..1 : 32 cols each

    bf16* sWhi = (bf16*)(smem + SW_HI);
    bf16* sWlo = (bf16*)(smem + SW_LO);
    for (int i = tid; i < 512 * 64; i += 544) {
        int k = i >> 6, n = i & 63;
        sWhi[k * W_LD + n] = g_WhHi[(size_t)k * NTOT + nc0 + n];
        sWlo[k * W_LD + n] = g_WhLo[(size_t)k * NTOT + nc0 + n];
    }
    bf16* sQW = (bf16*)(smem + SQW);
    for (int i = tid; i < 512 * 16; i += 544) {
        int k = i >> 4, c = i & 15;
        float v = Wq[(size_t)(512 + k) * NQV + (c & 7)];
        bf16 h = __float2bfloat16_rn(v);
        sQW[k * QW_LD + c] = (c < 8) ? h : __float2bfloat16_rn(v - __bfloat162float(h));
    }
    float* sBias = (float*)(smem + SBIAS);
    if (tid < 64) sBias[tid] = g_biasI[nc0 + tid];
    float* sWqhS = (float*)(smem + SWQHS);
    if (tid < 128) sWqhS[tid] = Wqh[(size_t)(tid >> 4) * HID + nt * 16 + (tid & 15)];
    float* sBqh = (float*)(smem + SBQH);
    if (tid < 16) sBqh[tid] = bqh[nt * 16 + tid];
    float* sTh = (float*)(smem + STH);
    if (tid < 32) {
        int g = tid >> 3, q = tid & 7;
        sTh[tid] = (g == 0) ? thf[q] : (g == 1) ? thi[q] : (g == 2) ? thu[q] : tho[q];
    }
    if (tid == 0) {
        #pragma unroll
        for (int s = 0; s < 3; ++s) {
            mbar_init(su + SMB_FULL + s * 8, 1);
            mbar_init(su + SMB_CONS + s * 8, 16);
        }
    }
    FENCE_ASYNC();
    float c_state[4];
    #pragma unroll
    for (int i = 0; i < 4; i++) c_state[i] = 0.f;
    __syncthreads();

    for (int t = 0; t < T_STEPS; ++t) {
        const int rbuf = t & 1, wbuf = rbuf ^ 1;

        // prefetch XP/XQ for this step (independent of h) — hides DRAM latency
        float4 xv0, xv1, xv2, xv3, xqa, xqb;
        if (tid < 512) {
            const int r = tid >> 2, qd = tid & 3;
            const float4* xp4 = (const float4*)(g_XP + ((size_t)t * BATCH + m0 + r) * NTOT + nc0 + qd * 16);
            xv0 = xp4[0]; xv1 = xp4[1]; xv2 = xp4[2]; xv3 = xp4[3];
            const float4* xqp = (const float4*)(g_XQ + ((size_t)t * BATCH + m0 + r) * NQV);
            xqa = xqp[0]; xqb = xqp[1];
        }

        if (tid == 512) {
            // --- producer: inter-block barrier (h ready), then stream 16 chunks ---
            if (t > 0) {
                __threadfence();
                unsigned gen = g_genA[mt];
                if (atomicAdd(&g_arr[mt], 1u) == 31u) {
                    g_arr[mt] = 0;
                    __threadfence();
                    g_genA[mt] = gen + 1;
                } else {
                    while (g_genA[mt] == gen) { }
                    __threadfence();
                }
            }
            const char* hSrc = (const char*)g_hT + (size_t)((rbuf * 4 + mt) * 16) * 17408;
            #pragma unroll
            for (int kc = 0; kc < 16; ++kc) {
                int s = kc % 3;
                int nu = t * ((s == 0) ? 6 : 5) + kc / 3;
                if (nu > 0) mbar_wait(su + SMB_CONS + s * 8, (nu - 1) & 1);
                unsigned mb = su + SMB_FULL + s * 8;
                mbar_expect(mb, 17408);
                bulk_cp(su + ST_A + s * ST_ABUF, hSrc + (size_t)kc * 17408, 17408, mb);
            }
        }

        wmma::fragment<wmma::accumulator, 16, 16, 16, float> acch[2], accx[2], accq;
        if (tid < 512) {
            #pragma unroll
            for (int j = 0; j < 2; j++) { wmma::fill_fragment(acch[j], 0.f); wmma::fill_fragment(accx[j], 0.f); }
            wmma::fill_fragment(accq, 0.f);

            #pragma unroll
            for (int kc = 0; kc < 16; ++kc) {
                int s = kc % 3;
                int nu = t * ((s == 0) ? 6 : 5) + kc / 3;
                mbar_wait(su + SMB_FULL + s * 8, nu & 1);

                const bf16* Ahi = (const bf16*)(smem + ST_A + s * ST_ABUF);
                const bf16* Alo = (const bf16*)(smem + ST_A + s * ST_ABUF + 8704);
                const int kb = kc * 32;
                #pragma unroll
                for (int ks = 0; ks < 2; ++ks) {
                    wmma::fragment<wmma::matrix_a, 16, 16, 16, bf16, wmma::col_major> ahi, alo;
                    wmma::load_matrix_sync(ahi, Ahi + (ks * 16) * A_LD + wr * 16, A_LD);
                    wmma::load_matrix_sync(alo, Alo + (ks * 16) * A_LD + wr * 16, A_LD);
                    #pragma unroll
                    for (int j = 0; j < 2; j++) {
                        wmma::fragment<wmma::matrix_b, 16, 16, 16, bf16, wmma::row_major> bhi, blo;
                        wmma::load_matrix_sync(bhi, sWhi + (kb + ks * 16) * W_LD + wc * 32 + j * 16, W_LD);
                        wmma::load_matrix_sync(blo, sWlo + (kb + ks * 16) * W_LD + wc * 32 + j * 16, W_LD);
                        wmma::mma_sync(acch[j], ahi, bhi, acch[j]);
                        wmma::mma_sync(accx[j], ahi, blo, accx[j]);
                        wmma::mma_sync(accx[j], alo, bhi, accx[j]);
                    }
                    if (wc == 0) {
                        wmma::fragment<wmma::matrix_b, 16, 16, 16, bf16, wmma::row_major> bq;
                        wmma::load_matrix_sync(bq, sQW + (kb + ks * 16) * QW_LD, QW_LD);
                        wmma::mma_sync(accq, ahi, bq, accq);
                        wmma::mma_sync(accq, alo, bq, accq);
                    }
                }
                if (lane == 0) mbar_arrive(su + SMB_CONS + s * 8);
            }
        }
        __syncthreads();   // all MMAs done; stage smem reusable as sP/sQm

        float* sP  = (float*)(smem + ST_A);
        float* sQm = (float*)(smem + ST_A + 34816);
        if (tid < 512) {
            #pragma unroll
            for (int j = 0; j < 2; j++) {
                #pragma unroll
                for (int e = 0; e < acch[j].num_elements; ++e) acch[j].x[e] += accx[j].x[e];
                wmma::store_matrix_sync(sP + (wr * 16) * SP_LD + wc * 32 + j * 16, acch[j], SP_LD, wmma::mem_row_major);
            }
            if (wc == 0)
                wmma::store_matrix_sync(sQm + (wr * 16) * 16, accq, 16, wmma::mem_row_major);
        }
        __syncthreads();

        if (tid < 512) {
            // phase1: thread = (row, gate): qin + cumprod(cos)
            const int r = tid >> 2;
            const int gq = tid & 3;
            float z[NQV];
            {
                float xqv[NQV] = {xqa.x, xqa.y, xqa.z, xqa.w, xqb.x, xqb.y, xqb.z, xqb.w};
                float run = 1.f;
                #pragma unroll
                for (int q = 0; q < NQV; ++q) {
                    float qin = sQm[r * 16 + q] + sQm[r * 16 + 8 + q] + xqv[q];
                    run *= __cosf(qin + sTh[gq * 8 + q]);
                    z[q] = run;
                }
            }
            float zz[4][NQV];
            {
                const int lb = lane & ~3;
                #pragma unroll
                for (int g = 0; g < 4; ++g)
                    #pragma unroll
                    for (int q = 0; q < NQV; ++q)
                        zz[g][q] = __shfl_sync(0xffffffffu, z[q], lb + g);
            }

            // phase2: thread = (row, col-quad): combine + LSTM update + h write
            const int qd = gq;
            const int rowg = m0 + r;
            const float* sPr = sP + r * SP_LD + qd * 16;
            const float* sBq_ = sBias + qd * 16;
            const size_t ob = ((size_t)t * BATCH + rowg) * HID;
            float4 xvv[4] = {xv0, xv1, xv2, xv3};
            #pragma unroll
            for (int jj = 0; jj < 4; ++jj) {
                int jl = qd * 4 + jj;
                int jg = nt * 16 + jl;
                float4 xvq = xvv[jj];
                float p0 = sPr[jj * 4 + 0] + xvq.x + sBq_[jj * 4 + 0];
                float p1 = sPr[jj * 4 + 1] + xvq.y + sBq_[jj * 4 + 1];
                float p2 = sPr[jj * 4 + 2] + xvq.z + sBq_[jj * 4 + 2];
                float p3 = sPr[jj * 4 + 3] + xvq.w + sBq_[jj * 4 + 3];
                float a0 = sBqh[jl], a1 = a0, a2 = a0, a3 = a0;
                #pragma unroll
                for (int q = 0; q < NQV; q++) {
                    float w = sWqhS[q * 16 + jl];
                    a0 += zz[0][q] * w;
                    a1 += zz[1][q] * w;
                    a2 += zz[2][q] * w;
                    a3 += zz[3][q] * w;
                }
                float f  = ALPHA_F * sigm(p0)  + ALPHB_F * sigm(a0);
                float ii = ALPHA_F * sigm(p1)  + ALPHB_F * sigm(a1);
                float gg = ALPHA_F * tanhf(p2) + ALPHB_F * tanhf(a2);
                float oo = ALPHA_F * sigm(p3)  + ALPHB_F * sigm(a3);
                float cn = f * c_state[jj] + ii * gg;
                float hn = oo * tanhf(cn);
                c_state[jj] = cn;
                out[ob + jg] = hn;
                bf16 hh = __float2bfloat16_rn(hn);
                bf16 hl = __float2bfloat16_rn(hn - __bfloat162float(hh));
                size_t hbase = (size_t)((wbuf * 4 + mt) * 16 + (jg >> 5)) * 8704
                             + (size_t)(jg & 31) * 136 + r;
                g_hT[hbase] = hh;
                g_hT[hbase + 4352] = hl;
                if (t == T_STEPS - 1 && tails) {
                    size_t outT = (size_t)T_STEPS * BATCH * HID;
                    out[outT + (size_t)rowg * HID + jg] = hn;
                    out[outT + (size_t)BATCH * HID + (size_t)rowg * HID + jg] = cn;
                }
            }
        }

        FENCE_ASYNC();      // order generic sP/sQm writes before next step's TMA
        __syncthreads();    // producer may now re-enter; h writes block-visible
    }
}

// ---------------- launch ------------------------------------------------------
extern "C" void kernel_launch(void* const* d_in, const int* in_sizes, int n_in,
                              void* d_out, int out_size)
{
    const float* inputs = (const float*)d_in[0];
    const float* Wf = (const float*)d_in[1];
    const float* bf_ = (const float*)d_in[2];
    const float* Wi = (const float*)d_in[3];
    const float* bi = (const float*)d_in[4];
    const float* Wu = (const float*)d_in[5];
    const float* bu = (const float*)d_in[6];
    const float* Wo = (const float*)d_in[7];
    const float* bo = (const float*)d_in[8];
    const float* Wq = (const float*)d_in[9];
    const float* bq = (const float*)d_in[10];
    const float* Wqh = (const float*)d_in[11];
    const float* bqh = (const float*)d_in[12];
    const float* th_f = (const float*)d_in[13];
    const float* th_i = (const float*)d_in[14];
    const float* th_u = (const float*)d_in[15];
    const float* th_o = (const float*)d_in[16];
    float* out = (float*)d_out;

    cudaFuncSetAttribute(gemm_x, cudaFuncAttributeMaxDynamicSharedMemorySize, GX_TOTAL);
    cudaFuncSetAttribute(qlstm_persistent, cudaFuncAttributeMaxDynamicSharedMemorySize, PS_TOTAL);

    const size_t outT = (size_t)T_STEPS * BATCH * HID;
    int tails = ((size_t)out_size >= outT + 2 * (size_t)BATCH * HID) ? 1 : 0;

    zero_state<<<(2 * 4 * 16 * 8704 + 255) / 256, 256>>>();
    cvt_x<<<(int)(((size_t)MROWS * DIM + 255) / 256), 256>>>(inputs);
    cvt_w<<<(512 * NTOT + 255) / 256, 256>>>(Wf, Wi, Wu, Wo, bf_, bi, bu, bo);
    xq_kernel<<<MROWS / 16, 512>>>(inputs, Wq, bq);
    gemm_x<<<dim3(16, MROWS / 128), 256, GX_TOTAL>>>();
    qlstm_persistent<<<NBLOCKS, 544, PS_TOTAL>>>(
        Wq, Wqh, bqh, th_f, th_i, th_u, th_o, out, tails);
}